// round 14
// baseline (speedup 1.0000x reference)
#include <cuda_runtime.h>
#include <cuda_bf16.h>
#include <cstdint>
#include <cstddef>

#define NTOK   8192      // B*S
#define DMODEL 1024
#define NFF    2048

// ---------------- scratch: pre-split bf16 (hi,lo) pairs ----------------
__device__ __nv_bfloat16 g_xnh[NTOK * DMODEL], g_xnl[NTOK * DMODEL];
__device__ __nv_bfloat16 g_qh [NTOK * DMODEL], g_ql [NTOK * DMODEL];
__device__ __nv_bfloat16 g_kh [NTOK * DMODEL], g_kl [NTOK * DMODEL];
__device__ __nv_bfloat16 g_vh [NTOK * DMODEL], g_vl [NTOK * DMODEL];
__device__ __nv_bfloat16 g_ath[NTOK * DMODEL], g_atl[NTOK * DMODEL];
__device__ __nv_bfloat16 g_hh [NTOK * DMODEL], g_hl [NTOK * DMODEL];
__device__ __nv_bfloat16 g_ffh[NTOK * NFF],    g_ffl[NTOK * NFF];
__device__ __nv_bfloat16 g_wqh[DMODEL * DMODEL], g_wql[DMODEL * DMODEL];
__device__ __nv_bfloat16 g_wkh[DMODEL * DMODEL], g_wkl[DMODEL * DMODEL];
__device__ __nv_bfloat16 g_wvh[DMODEL * DMODEL], g_wvl[DMODEL * DMODEL];
__device__ __nv_bfloat16 g_woh[DMODEL * DMODEL], g_wol[DMODEL * DMODEL];
__device__ __nv_bfloat16 g_f1h[DMODEL * NFF],    g_f1l[DMODEL * NFF];
__device__ __nv_bfloat16 g_f2h[NFF * DMODEL],    g_f2l[NFF * DMODEL];

// ---------------- helpers ----------------
__device__ __forceinline__ uint32_t smem_u32(const void* p) {
    return (uint32_t)__cvta_generic_to_shared(p);
}
__device__ __forceinline__ void cp16(uint32_t dst, const void* src) {
    asm volatile("cp.async.cg.shared.global [%0], [%1], 16;\n" :: "r"(dst), "l"(src));
}
__device__ __forceinline__ void cp_commit() {
    asm volatile("cp.async.commit_group;\n");
}
template <int N>
__device__ __forceinline__ void cp_wait() {
    asm volatile("cp.async.wait_group %0;\n" :: "n"(N));
}
__device__ __forceinline__ void ldsm_x4(uint32_t& r0, uint32_t& r1, uint32_t& r2,
                                        uint32_t& r3, uint32_t a) {
    asm volatile("ldmatrix.sync.aligned.m8n8.x4.shared.b16 {%0,%1,%2,%3}, [%4];\n"
                 : "=r"(r0), "=r"(r1), "=r"(r2), "=r"(r3) : "r"(a));
}
__device__ __forceinline__ void ldsm_x4t(uint32_t& r0, uint32_t& r1, uint32_t& r2,
                                         uint32_t& r3, uint32_t a) {
    asm volatile("ldmatrix.sync.aligned.m8n8.x4.trans.shared.b16 {%0,%1,%2,%3}, [%4];\n"
                 : "=r"(r0), "=r"(r1), "=r"(r2), "=r"(r3) : "r"(a));
}
__device__ __forceinline__ void mma16816(float* d, const uint32_t* a, const uint32_t* b) {
    asm volatile(
        "mma.sync.aligned.m16n8k16.row.col.f32.bf16.bf16.f32 "
        "{%0,%1,%2,%3}, {%4,%5,%6,%7}, {%8,%9}, {%0,%1,%2,%3};\n"
        : "+f"(d[0]), "+f"(d[1]), "+f"(d[2]), "+f"(d[3])
        : "r"(a[0]), "r"(a[1]), "r"(a[2]), "r"(a[3]), "r"(b[0]), "r"(b[1]));
}

// split 2 fp32 -> packed bf16 hi pair + lo pair
__device__ __forceinline__ void split2_pack(float v0, float v1,
                                            uint32_t& hp, uint32_t& lp) {
    __nv_bfloat16 h0 = __float2bfloat16(v0);
    __nv_bfloat16 h1 = __float2bfloat16(v1);
    __nv_bfloat16 l0 = __float2bfloat16(v0 - __bfloat162float(h0));
    __nv_bfloat16 l1 = __float2bfloat16(v1 - __bfloat162float(h1));
    hp = (uint32_t)__bfloat16_as_ushort(h0) | ((uint32_t)__bfloat16_as_ushort(h1) << 16);
    lp = (uint32_t)__bfloat16_as_ushort(l0) | ((uint32_t)__bfloat16_as_ushort(l1) << 16);
}
__device__ __forceinline__ void split4_pack(float4 f, uint2& hp, uint2& lp) {
    split2_pack(f.x, f.y, hp.x, lp.x);
    split2_pack(f.z, f.w, hp.y, lp.y);
}

// =====================================================================
// weight split: fp32 -> (hi,lo) bf16
// =====================================================================
__global__ __launch_bounds__(256)
void wsplit_kernel(const float4* __restrict__ in, uint2* __restrict__ oh,
                   uint2* __restrict__ ol, int n4)
{
    int i = blockIdx.x * 256 + threadIdx.x;
    if (i >= n4) return;
    uint2 hp, lp;
    split4_pack(in[i], hp, lp);
    oh[i] = hp;
    ol[i] = lp;
}

// =====================================================================
// LayerNorm: one block per row; output = (hi,lo) bf16 split
// =====================================================================
__global__ __launch_bounds__(256)
void ln_kernel(const float* __restrict__ x, const float* __restrict__ g,
               const float* __restrict__ b, float eps,
               __nv_bfloat16* __restrict__ oh, __nv_bfloat16* __restrict__ ol)
{
    const int tid = threadIdx.x;
    const size_t row = (size_t)blockIdx.x * DMODEL;
    const int c4 = tid * 4;

    float4 v = *(const float4*)(x + row + c4);
    float s = v.x + v.y + v.z + v.w;

    __shared__ float red[8];
    __shared__ float stat[2];

#pragma unroll
    for (int o = 16; o; o >>= 1) s += __shfl_xor_sync(0xffffffffu, s, o);
    if ((tid & 31) == 0) red[tid >> 5] = s;
    __syncthreads();
    if (tid == 0) {
        float t = 0.f;
#pragma unroll
        for (int i = 0; i < 8; i++) t += red[i];
        stat[0] = t * (1.f / DMODEL);
    }
    __syncthreads();
    const float mu = stat[0];

    float dx = v.x - mu, dy = v.y - mu, dz = v.z - mu, dw = v.w - mu;
    float s2 = dx * dx + dy * dy + dz * dz + dw * dw;
#pragma unroll
    for (int o = 16; o; o >>= 1) s2 += __shfl_xor_sync(0xffffffffu, s2, o);
    if ((tid & 31) == 0) red[tid >> 5] = s2;
    __syncthreads();
    if (tid == 0) {
        float t = 0.f;
#pragma unroll
        for (int i = 0; i < 8; i++) t += red[i];
        stat[1] = rsqrtf(t * (1.f / DMODEL) + eps);
    }
    __syncthreads();
    const float rstd = stat[1];

    float4 gg = *(const float4*)(g + c4);
    float4 bb = *(const float4*)(b + c4);
    float4 y;
    y.x = dx * rstd * gg.x + bb.x;
    y.y = dy * rstd * gg.y + bb.y;
    y.z = dz * rstd * gg.z + bb.z;
    y.w = dw * rstd * gg.w + bb.w;
    uint2 hp, lp;
    split4_pack(y, hp, lp);
    *(uint2*)&oh[row + c4] = hp;
    *(uint2*)&ol[row + c4] = lp;
}

// =====================================================================
// Tensor-core GEMM on pre-split bf16 operands, 4-stage cp.async pipeline.
//   C = Ah*Bh + Ah*Bl + Al*Bh  (fp32 accumulate)
//   MODE 0: split-out  (Chi/Clo = scale * AB)
//   MODE 1: fp32-out   (Cf = AB + res)
//   MODE 2: split-out  (Chi/Clo = relu(AB + bias))
//   MODE 3: fp32-out   (Cf = AB + bias + res)   (res may alias Cf)
// 128x128 tile, BK=16, 256 threads, 8 warps (2m x 4n, 64x32 warp tiles).
// Loader: each thread 4 x cp16 (Agh, Agl, Bgh, Bgl) -> full tile coverage:
//   A: arow=tid>>1 (0..127), ach=(tid&1)*8  -> 128x16 halves per half
//   B: brow=tid&15 (0..15),  bch=(tid>>4)*8 -> 16x128 halves per half
// smem pitches: A 24 halves, B 136 halves (odd 16B-chunk stride -> ldsm clean).
// =====================================================================
#define BK      16
#define APITCH  24
#define BPITCH  136
#define G_AH    0                      // byte offsets inside one stage
#define G_AL    6144                   // 128*24*2
#define G_BH    12288
#define G_BL    16640                  // +16*136*2
#define G_STAGE 20992
#define G_SMEM  (4 * G_STAGE)          // 83968 bytes

template <int MODE>
__device__ __forceinline__
void mma_gemm_body(const __nv_bfloat16* __restrict__ Agh, const __nv_bfloat16* __restrict__ Agl,
                   const __nv_bfloat16* __restrict__ Bgh, const __nv_bfloat16* __restrict__ Bgl,
                   const float* __restrict__ bias, const float* __restrict__ res,
                   float* Cf, __nv_bfloat16* Chi, __nv_bfloat16* Clo,
                   float scale, int N, int K, int bm, int bn)
{
    extern __shared__ __nv_bfloat16 dsm[];
    const uint32_t uBase = smem_u32(dsm);

    const int tid  = threadIdx.x;
    const int lane = tid & 31;
    const int warp = tid >> 5;
    const int wm   = (warp >> 2) * 64;
    const int wn   = (warp & 3) * 32;

    float acc[4][4][4];
#pragma unroll
    for (int i = 0; i < 4; i++)
#pragma unroll
        for (int j = 0; j < 4; j++)
#pragma unroll
            for (int r = 0; r < 4; r++) acc[i][j][r] = 0.f;

    // cp.async loader mapping (4 x 16B per thread per stage; full coverage)
    const int arow = tid >> 1;            // 0..127
    const int ach  = (tid & 1) * 8;       // 0 or 8 halves within the BK=16 row
    const int brow = tid & 15;            // 0..15
    const int bch  = (tid >> 4) * 8;      // 0..120 halves within the 128-col row
    const size_t a_src  = (size_t)(bm + arow) * K + ach;
    const size_t b_src0 = (size_t)brow * N + bn + bch;
    const uint32_t a_dst = (uint32_t)(arow * APITCH + ach) * 2;
    const uint32_t b_dst = (uint32_t)(brow * BPITCH + bch) * 2;

    const int niter = K / BK;

    auto issue = [&](int it, int s) {
        const int k0 = it * BK;
        const uint32_t st = uBase + (uint32_t)(s * G_STAGE);
        cp16(st + G_AH + a_dst, Agh + a_src + k0);
        cp16(st + G_AL + a_dst, Agl + a_src + k0);
        cp16(st + G_BH + b_dst, Bgh + b_src0 + (size_t)k0 * N);
        cp16(st + G_BL + b_dst, Bgl + b_src0 + (size_t)k0 * N);
    };

    // fragment lane offsets (bytes)
    const uint32_t a_off = (uint32_t)(((lane & 15) * APITCH + (lane >> 4) * 8) * 2);
    const uint32_t b_off = (uint32_t)((((lane & 7) + ((lane >> 3) & 1) * 8) * BPITCH
                                       + (lane >> 4) * 8) * 2);

    // prologue: stages 0..2
#pragma unroll
    for (int s = 0; s < 3; s++) { issue(s, s); cp_commit(); }
    cp_wait<2>();
    __syncthreads();

    for (int i = 0; i < niter; i++) {
        const uint32_t st = uBase + (uint32_t)((i & 3) * G_STAGE);

        // B fragments for 4 n-tiles (hi and lo)
        uint32_t bh[4][2], bl[4][2];
#pragma unroll
        for (int jp = 0; jp < 2; jp++) {
            const uint32_t nb = (uint32_t)((wn + 16 * jp) * 2);
            ldsm_x4t(bh[2 * jp][0], bh[2 * jp][1], bh[2 * jp + 1][0], bh[2 * jp + 1][1],
                     st + G_BH + b_off + nb);
            ldsm_x4t(bl[2 * jp][0], bl[2 * jp][1], bl[2 * jp + 1][0], bl[2 * jp + 1][1],
                     st + G_BL + b_off + nb);
        }

#pragma unroll
        for (int ii = 0; ii < 4; ii++) {
            const uint32_t mb = (uint32_t)((wm + 16 * ii) * APITCH * 2);
            uint32_t ah[4], al[4];
            ldsm_x4(ah[0], ah[1], ah[2], ah[3], st + G_AH + a_off + mb);
            ldsm_x4(al[0], al[1], al[2], al[3], st + G_AL + a_off + mb);
#pragma unroll
            for (int j = 0; j < 4; j++) {
                mma16816(acc[ii][j], ah, bh[j]);
                mma16816(acc[ii][j], ah, bl[j]);
                mma16816(acc[ii][j], al, bh[j]);
            }
        }

        const int nx = i + 3;
        if (nx < niter) issue(nx, nx & 3);
        cp_commit();
        cp_wait<2>();
        __syncthreads();
    }

    // epilogue
    const int r0 = lane >> 2;
    const int c0 = (lane & 3) * 2;
#pragma unroll
    for (int i = 0; i < 4; i++) {
        const int row = bm + wm + 16 * i + r0;
#pragma unroll
        for (int j = 0; j < 4; j++) {
            const int col = bn + wn + 8 * j + c0;
#pragma unroll
            for (int h = 0; h < 2; h++) {
                const size_t off = (size_t)(row + 8 * h) * N + col;
                float v0 = acc[i][j][2 * h + 0];
                float v1 = acc[i][j][2 * h + 1];
                if (MODE == 0) { v0 *= scale; v1 *= scale; }
                if (MODE == 1) { v0 += res[off]; v1 += res[off + 1]; }
                if (MODE == 2) {
                    v0 = fmaxf(v0 + bias[col], 0.f);
                    v1 = fmaxf(v1 + bias[col + 1], 0.f);
                }
                if (MODE == 3) {
                    v0 += bias[col] + res[off];
                    v1 += bias[col + 1] + res[off + 1];
                }
                if (MODE == 0 || MODE == 2) {
                    uint32_t hp, lp;
                    split2_pack(v0, v1, hp, lp);
                    *(uint32_t*)&Chi[off] = hp;
                    *(uint32_t*)&Clo[off] = lp;
                } else {
                    float2 o; o.x = v0; o.y = v1;
                    *(float2*)&Cf[off] = o;
                }
            }
        }
    }
}

template <int MODE>
__global__ __launch_bounds__(256)
void mma_gemm_kernel(const __nv_bfloat16* __restrict__ Agh, const __nv_bfloat16* __restrict__ Agl,
                     const __nv_bfloat16* __restrict__ Bgh, const __nv_bfloat16* __restrict__ Bgl,
                     const float* __restrict__ bias, const float* __restrict__ res,
                     float* Cf, __nv_bfloat16* Chi, __nv_bfloat16* Clo,
                     float scale, int N, int K)
{
    mma_gemm_body<MODE>(Agh, Agl, Bgh, Bgl, bias, res, Cf, Chi, Clo, scale,
                        N, K, blockIdx.y * 128, blockIdx.x * 128);
}

// Fused QKV: blockIdx.z picks (W, out); q prescaled by 1/sqrt(DK)=0.125.
__global__ __launch_bounds__(256)
void mma_qkv_kernel(const __nv_bfloat16* __restrict__ Agh, const __nv_bfloat16* __restrict__ Agl)
{
    const int z = blockIdx.z;
    const __nv_bfloat16* Bh = (z == 0) ? g_wqh : (z == 1) ? g_wkh : g_wvh;
    const __nv_bfloat16* Bl = (z == 0) ? g_wql : (z == 1) ? g_wkl : g_wvl;
    __nv_bfloat16* Ch = (z == 0) ? g_qh : (z == 1) ? g_kh : g_vh;
    __nv_bfloat16* Cl = (z == 0) ? g_ql : (z == 1) ? g_kl : g_vl;
    const float scale = (z == 0) ? 0.125f : 1.0f;
    mma_gemm_body<0>(Agh, Agl, Bh, Bl, nullptr, nullptr, nullptr, Ch, Cl, scale,
                     DMODEL, DMODEL, blockIdx.y * 128, blockIdx.x * 128);
}

// =====================================================================
// Tensor-core flash attention on pre-split bf16 Q/K/V (cp.async loads).
// Block: 128 threads (4 warps), one (b,h) head, 64-query tile, Bc=64.
// Warp owns 16 q-rows x all 64 keys -> warp-local softmax.
// smem tiles pitch 72 halves (9x16B, odd -> ldsm conflict-free):
//   Qh Ql Kh Kl Vh Vl Ph Pl, 9216 B each = 73728 B total.
// Output: att as (hi,lo) bf16 split.
// =====================================================================
#define ATTP 72
#define T_QH 0
#define T_QL 1
#define T_KH 2
#define T_KL 3
#define T_VH 4
#define T_VL 5
#define T_PH 6
#define T_PL 7
#define ATT_TILE_B (64 * ATTP * 2)          // 9216 bytes
#define ATT_SMEM_BYTES (8 * ATT_TILE_B)     // 73728 bytes

__global__ __launch_bounds__(128)
void attn_mma_kernel(const __nv_bfloat16* __restrict__ Qh_g, const __nv_bfloat16* __restrict__ Ql_g,
                     const __nv_bfloat16* __restrict__ Kh_g, const __nv_bfloat16* __restrict__ Kl_g,
                     const __nv_bfloat16* __restrict__ Vh_g, const __nv_bfloat16* __restrict__ Vl_g,
                     __nv_bfloat16* __restrict__ Oh_g, __nv_bfloat16* __restrict__ Ol_g)
{
    extern __shared__ __nv_bfloat16 sh[];
    const uint32_t uB = smem_u32(sh);
    __nv_bfloat16* Ph = sh + T_PH * 64 * ATTP;
    __nv_bfloat16* Pl = sh + T_PL * 64 * ATTP;

    const int tid  = threadIdx.x;
    const int lane = tid & 31;
    const int warp = tid >> 5;
    const int qt   = blockIdx.x;            // 0..31
    const int bh   = blockIdx.y;            // 0..63
    const size_t base = ((size_t)(bh >> 4) * 2048) * DMODEL + (size_t)(bh & 15) * 64;
    const size_t qoff = base + (size_t)qt * 64 * DMODEL;

    // cp.async loader mapping: row lr (0..63), 32-half group lh, 4 chunks
    const int lr = tid >> 1;
    const int lh = (tid & 1) * 32;
    const uint32_t dst_row = (uint32_t)(lr * ATTP + lh) * 2;

    // issue Q (grouped with kt=0's K/V commit)
#pragma unroll
    for (int c = 0; c < 4; c++) {
        cp16(uB + T_QH * ATT_TILE_B + dst_row + 16 * c, Qh_g + qoff + (size_t)lr * DMODEL + lh + 8 * c);
        cp16(uB + T_QL * ATT_TILE_B + dst_row + 16 * c, Ql_g + qoff + (size_t)lr * DMODEL + lh + 8 * c);
    }

    const uint32_t frag_a = (uint32_t)(((lane & 15) * ATTP + (lane >> 4) * 8) * 2);
    const uint32_t frag_b = (uint32_t)((((lane & 7) + ((lane >> 3) & 1) * 8) * ATTP
                                        + (lane >> 4) * 8) * 2);
    const uint32_t warp_m = (uint32_t)(warp * 16 * ATTP * 2);

    float o[8][4];
#pragma unroll
    for (int j = 0; j < 8; j++)
#pragma unroll
        for (int r = 0; r < 4; r++) o[j][r] = 0.f;
    float mrun[2] = {-1e30f, -1e30f};
    float lrun[2] = {0.f, 0.f};

    for (int kt = 0; kt < 32; kt++) {
        __syncthreads();   // previous tile fully consumed
        {
            const size_t src = base + (size_t)(kt * 64 + lr) * DMODEL + lh;
#pragma unroll
            for (int c = 0; c < 4; c++) {
                cp16(uB + T_KH * ATT_TILE_B + dst_row + 16 * c, Kh_g + src + 8 * c);
                cp16(uB + T_KL * ATT_TILE_B + dst_row + 16 * c, Kl_g + src + 8 * c);
                cp16(uB + T_VH * ATT_TILE_B + dst_row + 16 * c, Vh_g + src + 8 * c);
                cp16(uB + T_VL * ATT_TILE_B + dst_row + 16 * c, Vl_g + src + 8 * c);
            }
        }
        cp_commit();
        cp_wait<0>();
        __syncthreads();

        // ---- S = Q @ K^T (Q prescaled at QKV epilogue) ----
        float s[8][4];
#pragma unroll
        for (int j = 0; j < 8; j++)
#pragma unroll
            for (int r = 0; r < 4; r++) s[j][r] = 0.f;

#pragma unroll
        for (int ks = 0; ks < 4; ks++) {
            const uint32_t ko = (uint32_t)(ks * 32);   // 16 halves = 32 bytes
            uint32_t qh[4], ql[4];
            ldsm_x4(qh[0], qh[1], qh[2], qh[3], uB + T_QH * ATT_TILE_B + frag_a + warp_m + ko);
            ldsm_x4(ql[0], ql[1], ql[2], ql[3], uB + T_QL * ATT_TILE_B + frag_a + warp_m + ko);
#pragma unroll
            for (int jp = 0; jp < 4; jp++) {
                const uint32_t nb = (uint32_t)(jp * 16 * ATTP * 2);
                uint32_t h0, h1, h2, h3, l0, l1, l2, l3;
                ldsm_x4(h0, h1, h2, h3, uB + T_KH * ATT_TILE_B + frag_a + nb + ko);
                ldsm_x4(l0, l1, l2, l3, uB + T_KL * ATT_TILE_B + frag_a + nb + ko);
                uint32_t bh0[2] = {h0, h2}, bh1[2] = {h1, h3};
                uint32_t bl0[2] = {l0, l2}, bl1[2] = {l1, l3};
                mma16816(s[2 * jp],     qh, bh0);
                mma16816(s[2 * jp],     qh, bl0);
                mma16816(s[2 * jp],     ql, bh0);
                mma16816(s[2 * jp + 1], qh, bh1);
                mma16816(s[2 * jp + 1], qh, bl1);
                mma16816(s[2 * jp + 1], ql, bh1);
            }
        }

        // ---- online softmax (warp-local rows) + split P -> smem ----
#pragma unroll
        for (int h = 0; h < 2; h++) {
            float mt = -1e30f;
#pragma unroll
            for (int j = 0; j < 8; j++)
                mt = fmaxf(mt, fmaxf(s[j][2 * h], s[j][2 * h + 1]));
            mt = fmaxf(mt, __shfl_xor_sync(0xffffffffu, mt, 1));
            mt = fmaxf(mt, __shfl_xor_sync(0xffffffffu, mt, 2));
            const float mnew = fmaxf(mrun[h], mt);
            const float corr = __expf(mrun[h] - mnew);
            mrun[h] = mnew;

            float ls = 0.f;
            const int prow = warp * 16 + (lane >> 2) + 8 * h;
            const int pcb  = 2 * (lane & 3);
#pragma unroll
            for (int j = 0; j < 8; j++) {
                float p0 = __expf(s[j][2 * h]     - mnew);
                float p1 = __expf(s[j][2 * h + 1] - mnew);
                ls += p0 + p1;
                uint32_t hp, lp;
                split2_pack(p0, p1, hp, lp);
                const int idx = prow * ATTP + 8 * j + pcb;
                *(uint32_t*)&Ph[idx] = hp;
                *(uint32_t*)&Pl[idx] = lp;
            }
            ls += __shfl_xor_sync(0xffffffffu, ls, 1);
            ls += __shfl_xor_sync(0xffffffffu, ls, 2);
            lrun[h] = lrun[h] * corr + ls;
#pragma unroll
            for (int j = 0; j < 8; j++) {
                o[j][2 * h]     *= corr;
                o[j][2 * h + 1] *= corr;
            }
        }
        __syncwarp();   // P rows are warp-private; make stores visible to ldsm

        // ---- O += P @ V ----
#pragma unroll
        for (int ks = 0; ks < 4; ks++) {
            const uint32_t ko  = (uint32_t)(ks * 32);
            const uint32_t kvo = (uint32_t)(ks * 16 * ATTP * 2);
            uint32_t ph[4], pl[4];
            ldsm_x4(ph[0], ph[1], ph[2], ph[3], uB + T_PH * ATT_TILE_B + frag_a + warp_m + ko);
            ldsm_x4(pl[0], pl[1], pl[2], pl[3], uB + T_PL * ATT_TILE_B + frag_a + warp_m + ko);
#pragma unroll
            for (int jp = 0; jp < 4; jp++) {
                const uint32_t nb = (uint32_t)(16 * jp * 2);
                uint32_t h0, h1, h2, h3, l0, l1, l2, l3;
                ldsm_x4t(h0, h1, h2, h3, uB + T_VH * ATT_TILE_B + frag_b + kvo + nb);
                ldsm_x4t(l0, l1, l2, l3, uB + T_VL * ATT_TILE_B + frag_b + kvo + nb);
                uint32_t bh0[2] = {h0, h1}, bh1[2] = {h2, h3};
                uint32_t bl0[2] = {l0, l1}, bl1[2] = {l2, l3};
                mma16816(o[2 * jp],     ph, bh0);
                mma16816(o[2 * jp],     ph, bl0);
                mma16816(o[2 * jp],     pl, bh0);
                mma16816(o[2 * jp + 1], ph, bh1);
                mma16816(o[2 * jp + 1], ph, bl1);
                mma16816(o[2 * jp + 1], pl, bh1);
            }
        }
    }

    // ---- epilogue: (O / l) -> split bf16 ----
#pragma unroll
    for (int h = 0; h < 2; h++) {
        const float inv = 1.f / lrun[h];
        const int row = warp * 16 + (lane >> 2) + 8 * h;
#pragma unroll
        for (int j = 0; j < 8; j++) {
            const int col = 8 * j + 2 * (lane & 3);
            const size_t off = qoff + (size_t)row * DMODEL + col;
            uint32_t hp, lp;
            split2_pack(o[j][2 * h] * inv, o[j][2 * h + 1] * inv, hp, lp);
            *(uint32_t*)&Oh_g[off] = hp;
            *(uint32_t*)&Ol_g[off] = lp;
        }
    }
}

// =====================================================================
// launch
// =====================================================================
extern "C" void kernel_launch(void* const* d_in, const int* in_sizes, int n_in,
                              void* d_out, int out_size)
{
    (void)in_sizes; (void)n_in; (void)out_size;
    const float* x    = (const float*)d_in[0];
    const float* Wq   = (const float*)d_in[1];
    const float* Wk   = (const float*)d_in[2];
    const float* Wv   = (const float*)d_in[3];
    const float* Wo   = (const float*)d_in[4];
    const float* ln1g = (const float*)d_in[5];
    const float* ln1b = (const float*)d_in[6];
    const float* fc1w = (const float*)d_in[7];
    const float* fc1b = (const float*)d_in[8];
    const float* fc2w = (const float*)d_in[9];
    const float* fc2b = (const float*)d_in[10];
    const float* ln2g = (const float*)d_in[11];
    const float* ln2b = (const float*)d_in[12];
    float* out = (float*)d_out;

    void *xnh, *xnl, *qh, *ql, *kh, *kl, *vh, *vl, *ath, *atl, *hh, *hl, *ffh, *ffl;
    void *wqh, *wql, *wkh, *wkl, *wvh, *wvl, *woh, *wol, *f1h, *f1l, *f2h, *f2l;
    cudaGetSymbolAddress(&xnh, g_xnh); cudaGetSymbolAddress(&xnl, g_xnl);
    cudaGetSymbolAddress(&qh,  g_qh);  cudaGetSymbolAddress(&ql,  g_ql);
    cudaGetSymbolAddress(&kh,  g_kh);  cudaGetSymbolAddress(&kl,  g_kl);
    cudaGetSymbolAddress(&vh,  g_vh);  cudaGetSymbolAddress(&vl,  g_vl);
    cudaGetSymbolAddress(&ath, g_ath); cudaGetSymbolAddress(&atl, g_atl);
    cudaGetSymbolAddress(&hh,  g_hh);  cudaGetSymbolAddress(&hl,  g_hl);
    cudaGetSymbolAddress(&ffh, g_ffh); cudaGetSymbolAddress(&ffl, g_ffl);
    cudaGetSymbolAddress(&wqh, g_wqh); cudaGetSymbolAddress(&wql, g_wql);
    cudaGetSymbolAddress(&wkh, g_wkh); cudaGetSymbolAddress(&wkl, g_wkl);
    cudaGetSymbolAddress(&wvh, g_wvh); cudaGetSymbolAddress(&wvl, g_wvl);
    cudaGetSymbolAddress(&woh, g_woh); cudaGetSymbolAddress(&wol, g_wol);
    cudaGetSymbolAddress(&f1h, g_f1h); cudaGetSymbolAddress(&f1l, g_f1l);
    cudaGetSymbolAddress(&f2h, g_f2h); cudaGetSymbolAddress(&f2l, g_f2l);

    // dynamic smem opt-in (idempotent)
    cudaFuncSetAttribute(mma_gemm_kernel<1>, cudaFuncAttributeMaxDynamicSharedMemorySize, G_SMEM);
    cudaFuncSetAttribute(mma_gemm_kernel<2>, cudaFuncAttributeMaxDynamicSharedMemorySize, G_SMEM);
    cudaFuncSetAttribute(mma_gemm_kernel<3>, cudaFuncAttributeMaxDynamicSharedMemorySize, G_SMEM);
    cudaFuncSetAttribute(mma_qkv_kernel,     cudaFuncAttributeMaxDynamicSharedMemorySize, G_SMEM);
    cudaFuncSetAttribute(attn_mma_kernel,    cudaFuncAttributeMaxDynamicSharedMemorySize, ATT_SMEM_BYTES);

    // 0) split weights -> (hi,lo) bf16
    const int nD = DMODEL * DMODEL / 4;   // 262144
    const int nF = DMODEL * NFF / 4;      // 524288
    wsplit_kernel<<<nD / 256, 256>>>((const float4*)Wq, (uint2*)wqh, (uint2*)wql, nD);
    wsplit_kernel<<<nD / 256, 256>>>((const float4*)Wk, (uint2*)wkh, (uint2*)wkl, nD);
    wsplit_kernel<<<nD / 256, 256>>>((const float4*)Wv, (uint2*)wvh, (uint2*)wvl, nD);
    wsplit_kernel<<<nD / 256, 256>>>((const float4*)Wo, (uint2*)woh, (uint2*)wol, nD);
    wsplit_kernel<<<nF / 256, 256>>>((const float4*)fc1w, (uint2*)f1h, (uint2*)f1l, nF);
    wsplit_kernel<<<nF / 256, 256>>>((const float4*)fc2w, (uint2*)f2h, (uint2*)f2l, nF);

    // 1) LN1 -> xn (hi,lo)
    ln_kernel<<<NTOK, 256>>>(x, ln1g, ln1b, 1e-5f,
                             (__nv_bfloat16*)xnh, (__nv_bfloat16*)xnl);

    // 2) fused QKV -> q,k,v (hi,lo); q prescaled by 0.125
    dim3 gQKV(DMODEL / 128, NTOK / 128, 3);
    mma_qkv_kernel<<<gQKV, 256, G_SMEM>>>((const __nv_bfloat16*)xnh, (const __nv_bfloat16*)xnl);

    // 3) attention -> att (hi,lo)
    attn_mma_kernel<<<dim3(32, 64), 128, ATT_SMEM_BYTES>>>(
        (const __nv_bfloat16*)qh, (const __nv_bfloat16*)ql,
        (const __nv_bfloat16*)kh, (const __nv_bfloat16*)kl,
        (const __nv_bfloat16*)vh, (const __nv_bfloat16*)vl,
        (__nv_bfloat16*)ath, (__nv_bfloat16*)atl);

    // 4) out = att @ Wo + x   (fp32)
    dim3 gD(DMODEL / 128, NTOK / 128);
    mma_gemm_kernel<1><<<gD, 256, G_SMEM>>>(
        (const __nv_bfloat16*)ath, (const __nv_bfloat16*)atl,
        (const __nv_bfloat16*)woh, (const __nv_bfloat16*)wol,
        nullptr, x, out, nullptr, nullptr, 1.f, DMODEL, DMODEL);

    // 5) LN2 (eps 1e-6) -> h (hi,lo)
    ln_kernel<<<NTOK, 256>>>(out, ln2g, ln2b, 1e-6f,
                             (__nv_bfloat16*)hh, (__nv_bfloat16*)hl);

    // 6) ff = relu(h @ fc1_w + fc1_b) -> (hi,lo)
    dim3 gF(NFF / 128, NTOK / 128);
    mma_gemm_kernel<2><<<gF, 256, G_SMEM>>>(
        (const __nv_bfloat16*)hh, (const __nv_bfloat16*)hl,
        (const __nv_bfloat16*)f1h, (const __nv_bfloat16*)f1l,
        fc1b, nullptr, nullptr, (__nv_bfloat16*)ffh, (__nv_bfloat16*)ffl,
        1.f, NFF, DMODEL);

    // 7) out += ff @ fc2_w + fc2_b   (fp32, in-place accumulate)
    mma_gemm_kernel<3><<<gD, 256, G_SMEM>>>(
        (const __nv_bfloat16*)ffh, (const __nv_bfloat16*)ffl,
        (const __nv_bfloat16*)f2h, (const __nv_bfloat16*)f2l,
        fc2b, out, out, nullptr, nullptr, 1.f, DMODEL, NFF);
}

// round 15
// speedup vs baseline: 1.6541x; 1.6541x over previous
#include <cuda_runtime.h>
#include <cuda_bf16.h>
#include <cstdint>
#include <cstddef>

#define NTOK   8192      // B*S
#define DMODEL 1024
#define NFF    2048

// ---------------- scratch: pre-split bf16 (hi,lo) pairs ----------------
__device__ __nv_bfloat16 g_xnh[NTOK * DMODEL], g_xnl[NTOK * DMODEL];
__device__ __nv_bfloat16 g_qh [NTOK * DMODEL], g_ql [NTOK * DMODEL];
__device__ __nv_bfloat16 g_kh [NTOK * DMODEL], g_kl [NTOK * DMODEL];
__device__ __nv_bfloat16 g_vh [NTOK * DMODEL], g_vl [NTOK * DMODEL];
__device__ __nv_bfloat16 g_ath[NTOK * DMODEL], g_atl[NTOK * DMODEL];
__device__ __nv_bfloat16 g_hh [NTOK * DMODEL], g_hl [NTOK * DMODEL];
__device__ __nv_bfloat16 g_ffh[NTOK * NFF],    g_ffl[NTOK * NFF];
__device__ __nv_bfloat16 g_wqh[DMODEL * DMODEL], g_wql[DMODEL * DMODEL];
__device__ __nv_bfloat16 g_wkh[DMODEL * DMODEL], g_wkl[DMODEL * DMODEL];
__device__ __nv_bfloat16 g_wvh[DMODEL * DMODEL], g_wvl[DMODEL * DMODEL];
__device__ __nv_bfloat16 g_woh[DMODEL * DMODEL], g_wol[DMODEL * DMODEL];
__device__ __nv_bfloat16 g_f1h[DMODEL * NFF],    g_f1l[DMODEL * NFF];
__device__ __nv_bfloat16 g_f2h[NFF * DMODEL],    g_f2l[NFF * DMODEL];

// ---------------- helpers ----------------
__device__ __forceinline__ uint32_t smem_u32(const void* p) {
    return (uint32_t)__cvta_generic_to_shared(p);
}
__device__ __forceinline__ void cp16(uint32_t dst, const void* src) {
    asm volatile("cp.async.cg.shared.global [%0], [%1], 16;\n" :: "r"(dst), "l"(src));
}
__device__ __forceinline__ void cp_commit() {
    asm volatile("cp.async.commit_group;\n");
}
template <int N>
__device__ __forceinline__ void cp_wait() {
    asm volatile("cp.async.wait_group %0;\n" :: "n"(N));
}
__device__ __forceinline__ void ldsm_x4(uint32_t& r0, uint32_t& r1, uint32_t& r2,
                                        uint32_t& r3, uint32_t a) {
    asm volatile("ldmatrix.sync.aligned.m8n8.x4.shared.b16 {%0,%1,%2,%3}, [%4];\n"
                 : "=r"(r0), "=r"(r1), "=r"(r2), "=r"(r3) : "r"(a));
}
__device__ __forceinline__ void ldsm_x4t(uint32_t& r0, uint32_t& r1, uint32_t& r2,
                                         uint32_t& r3, uint32_t a) {
    asm volatile("ldmatrix.sync.aligned.m8n8.x4.trans.shared.b16 {%0,%1,%2,%3}, [%4];\n"
                 : "=r"(r0), "=r"(r1), "=r"(r2), "=r"(r3) : "r"(a));
}
__device__ __forceinline__ void mma16816(float* d, const uint32_t* a, const uint32_t* b) {
    asm volatile(
        "mma.sync.aligned.m16n8k16.row.col.f32.bf16.bf16.f32 "
        "{%0,%1,%2,%3}, {%4,%5,%6,%7}, {%8,%9}, {%0,%1,%2,%3};\n"
        : "+f"(d[0]), "+f"(d[1]), "+f"(d[2]), "+f"(d[3])
        : "r"(a[0]), "r"(a[1]), "r"(a[2]), "r"(a[3]), "r"(b[0]), "r"(b[1]));
}

// split 2 fp32 -> packed bf16 hi pair + lo pair
__device__ __forceinline__ void split2_pack(float v0, float v1,
                                            uint32_t& hp, uint32_t& lp) {
    __nv_bfloat16 h0 = __float2bfloat16(v0);
    __nv_bfloat16 h1 = __float2bfloat16(v1);
    __nv_bfloat16 l0 = __float2bfloat16(v0 - __bfloat162float(h0));
    __nv_bfloat16 l1 = __float2bfloat16(v1 - __bfloat162float(h1));
    hp = (uint32_t)__bfloat16_as_ushort(h0) | ((uint32_t)__bfloat16_as_ushort(h1) << 16);
    lp = (uint32_t)__bfloat16_as_ushort(l0) | ((uint32_t)__bfloat16_as_ushort(l1) << 16);
}
__device__ __forceinline__ void split4_pack(float4 f, uint2& hp, uint2& lp) {
    split2_pack(f.x, f.y, hp.x, lp.x);
    split2_pack(f.z, f.w, hp.y, lp.y);
}

// =====================================================================
// weight split: fp32 -> (hi,lo) bf16
// =====================================================================
__global__ __launch_bounds__(256)
void wsplit_kernel(const float4* __restrict__ in, uint2* __restrict__ oh,
                   uint2* __restrict__ ol, int n4)
{
    int i = blockIdx.x * 256 + threadIdx.x;
    if (i >= n4) return;
    uint2 hp, lp;
    split4_pack(in[i], hp, lp);
    oh[i] = hp;
    ol[i] = lp;
}

// =====================================================================
// LayerNorm: one block per row; output = (hi,lo) bf16 split
// =====================================================================
__global__ __launch_bounds__(256)
void ln_kernel(const float* __restrict__ x, const float* __restrict__ g,
               const float* __restrict__ b, float eps,
               __nv_bfloat16* __restrict__ oh, __nv_bfloat16* __restrict__ ol)
{
    const int tid = threadIdx.x;
    const size_t row = (size_t)blockIdx.x * DMODEL;
    const int c4 = tid * 4;

    float4 v = *(const float4*)(x + row + c4);
    float s = v.x + v.y + v.z + v.w;

    __shared__ float red[8];
    __shared__ float stat[2];

#pragma unroll
    for (int o = 16; o; o >>= 1) s += __shfl_xor_sync(0xffffffffu, s, o);
    if ((tid & 31) == 0) red[tid >> 5] = s;
    __syncthreads();
    if (tid == 0) {
        float t = 0.f;
#pragma unroll
        for (int i = 0; i < 8; i++) t += red[i];
        stat[0] = t * (1.f / DMODEL);
    }
    __syncthreads();
    const float mu = stat[0];

    float dx = v.x - mu, dy = v.y - mu, dz = v.z - mu, dw = v.w - mu;
    float s2 = dx * dx + dy * dy + dz * dz + dw * dw;
#pragma unroll
    for (int o = 16; o; o >>= 1) s2 += __shfl_xor_sync(0xffffffffu, s2, o);
    if ((tid & 31) == 0) red[tid >> 5] = s2;
    __syncthreads();
    if (tid == 0) {
        float t = 0.f;
#pragma unroll
        for (int i = 0; i < 8; i++) t += red[i];
        stat[1] = rsqrtf(t * (1.f / DMODEL) + eps);
    }
    __syncthreads();
    const float rstd = stat[1];

    float4 gg = *(const float4*)(g + c4);
    float4 bb = *(const float4*)(b + c4);
    float4 y;
    y.x = dx * rstd * gg.x + bb.x;
    y.y = dy * rstd * gg.y + bb.y;
    y.z = dz * rstd * gg.z + bb.z;
    y.w = dw * rstd * gg.w + bb.w;
    uint2 hp, lp;
    split4_pack(y, hp, lp);
    *(uint2*)&oh[row + c4] = hp;
    *(uint2*)&ol[row + c4] = lp;
}

// =====================================================================
// Tensor-core GEMM on pre-split bf16 operands, 4-stage cp.async pipeline.
//   C = Ah*Bh + Ah*Bl + Al*Bh  (fp32 accumulate)
//   MODE 0: split-out  (Chi/Clo = scale * AB)
//   MODE 1: fp32-out   (Cf = AB + res)
//   MODE 2: split-out  (Chi/Clo = relu(AB + bias))
//   MODE 3: fp32-out   (Cf = AB + bias + res)   (res may alias Cf)
// 128x128 tile, BK=16, 256 threads, 8 warps (2m x 4n, 64x32 warp tiles).
// Loader (COALESCED): each thread 4 x cp16 (Agh, Agl, Bgh, Bgl):
//   A: arow=tid>>1, ach=(tid&1)*8   -> thread pair covers one 32B row chunk
//   B: brow=tid>>4, bch=(tid&15)*8  -> 16 consecutive threads cover 256B of
//      ONE row (this was reversed in R13 -> 8x wavefront traffic -> regression)
// smem pitches: A 24 halves, B 136 halves (odd 16B-chunk stride -> ldsm clean).
// =====================================================================
#define BK      16
#define APITCH  24
#define BPITCH  136
#define G_AH    0                      // byte offsets inside one stage
#define G_AL    6144                   // 128*24*2
#define G_BH    12288
#define G_BL    16640                  // +16*136*2
#define G_STAGE 20992
#define G_SMEM  (4 * G_STAGE)          // 83968 bytes

template <int MODE>
__device__ __forceinline__
void mma_gemm_body(const __nv_bfloat16* __restrict__ Agh, const __nv_bfloat16* __restrict__ Agl,
                   const __nv_bfloat16* __restrict__ Bgh, const __nv_bfloat16* __restrict__ Bgl,
                   const float* __restrict__ bias, const float* __restrict__ res,
                   float* Cf, __nv_bfloat16* Chi, __nv_bfloat16* Clo,
                   float scale, int N, int K, int bm, int bn)
{
    extern __shared__ __nv_bfloat16 dsm[];
    const uint32_t uBase = smem_u32(dsm);

    const int tid  = threadIdx.x;
    const int lane = tid & 31;
    const int warp = tid >> 5;
    const int wm   = (warp >> 2) * 64;
    const int wn   = (warp & 3) * 32;

    float acc[4][4][4];
#pragma unroll
    for (int i = 0; i < 4; i++)
#pragma unroll
        for (int j = 0; j < 4; j++)
#pragma unroll
            for (int r = 0; r < 4; r++) acc[i][j][r] = 0.f;

    // cp.async loader mapping (4 x 16B per thread per stage; coalesced)
    const int arow = tid >> 1;            // 0..127
    const int ach  = (tid & 1) * 8;       // 0 or 8 halves within the BK=16 row
    const int brow = tid >> 4;            // 0..15   (16 threads share one row)
    const int bch  = (tid & 15) * 8;      // 0..120  (consecutive 16B chunks)
    const size_t a_src  = (size_t)(bm + arow) * K + ach;
    const size_t b_src0 = (size_t)brow * N + bn + bch;
    const uint32_t a_dst = (uint32_t)(arow * APITCH + ach) * 2;
    const uint32_t b_dst = (uint32_t)(brow * BPITCH + bch) * 2;

    const int niter = K / BK;

    auto issue = [&](int it, int s) {
        const int k0 = it * BK;
        const uint32_t st = uBase + (uint32_t)(s * G_STAGE);
        cp16(st + G_AH + a_dst, Agh + a_src + k0);
        cp16(st + G_AL + a_dst, Agl + a_src + k0);
        cp16(st + G_BH + b_dst, Bgh + b_src0 + (size_t)k0 * N);
        cp16(st + G_BL + b_dst, Bgl + b_src0 + (size_t)k0 * N);
    };

    // fragment lane offsets (bytes)
    const uint32_t a_off = (uint32_t)(((lane & 15) * APITCH + (lane >> 4) * 8) * 2);
    const uint32_t b_off = (uint32_t)((((lane & 7) + ((lane >> 3) & 1) * 8) * BPITCH
                                       + (lane >> 4) * 8) * 2);

    // prologue: stages 0..2
#pragma unroll
    for (int s = 0; s < 3; s++) { issue(s, s); cp_commit(); }
    cp_wait<2>();
    __syncthreads();

    for (int i = 0; i < niter; i++) {
        const uint32_t st = uBase + (uint32_t)((i & 3) * G_STAGE);

        // B fragments for 4 n-tiles (hi and lo)
        uint32_t bh[4][2], bl[4][2];
#pragma unroll
        for (int jp = 0; jp < 2; jp++) {
            const uint32_t nb = (uint32_t)((wn + 16 * jp) * 2);
            ldsm_x4t(bh[2 * jp][0], bh[2 * jp][1], bh[2 * jp + 1][0], bh[2 * jp + 1][1],
                     st + G_BH + b_off + nb);
            ldsm_x4t(bl[2 * jp][0], bl[2 * jp][1], bl[2 * jp + 1][0], bl[2 * jp + 1][1],
                     st + G_BL + b_off + nb);
        }

#pragma unroll
        for (int ii = 0; ii < 4; ii++) {
            const uint32_t mb = (uint32_t)((wm + 16 * ii) * APITCH * 2);
            uint32_t ah[4], al[4];
            ldsm_x4(ah[0], ah[1], ah[2], ah[3], st + G_AH + a_off + mb);
            ldsm_x4(al[0], al[1], al[2], al[3], st + G_AL + a_off + mb);
#pragma unroll
            for (int j = 0; j < 4; j++) {
                mma16816(acc[ii][j], ah, bh[j]);
                mma16816(acc[ii][j], ah, bl[j]);
                mma16816(acc[ii][j], al, bh[j]);
            }
        }

        const int nx = i + 3;
        if (nx < niter) issue(nx, nx & 3);
        cp_commit();
        cp_wait<2>();
        __syncthreads();
    }

    // epilogue
    const int r0 = lane >> 2;
    const int c0 = (lane & 3) * 2;
#pragma unroll
    for (int i = 0; i < 4; i++) {
        const int row = bm + wm + 16 * i + r0;
#pragma unroll
        for (int j = 0; j < 4; j++) {
            const int col = bn + wn + 8 * j + c0;
#pragma unroll
            for (int h = 0; h < 2; h++) {
                const size_t off = (size_t)(row + 8 * h) * N + col;
                float v0 = acc[i][j][2 * h + 0];
                float v1 = acc[i][j][2 * h + 1];
                if (MODE == 0) { v0 *= scale; v1 *= scale; }
                if (MODE == 1) { v0 += res[off]; v1 += res[off + 1]; }
                if (MODE == 2) {
                    v0 = fmaxf(v0 + bias[col], 0.f);
                    v1 = fmaxf(v1 + bias[col + 1], 0.f);
                }
                if (MODE == 3) {
                    v0 += bias[col] + res[off];
                    v1 += bias[col + 1] + res[off + 1];
                }
                if (MODE == 0 || MODE == 2) {
                    uint32_t hp, lp;
                    split2_pack(v0, v1, hp, lp);
                    *(uint32_t*)&Chi[off] = hp;
                    *(uint32_t*)&Clo[off] = lp;
                } else {
                    float2 o; o.x = v0; o.y = v1;
                    *(float2*)&Cf[off] = o;
                }
            }
        }
    }
}

template <int MODE>
__global__ __launch_bounds__(256)
void mma_gemm_kernel(const __nv_bfloat16* __restrict__ Agh, const __nv_bfloat16* __restrict__ Agl,
                     const __nv_bfloat16* __restrict__ Bgh, const __nv_bfloat16* __restrict__ Bgl,
                     const float* __restrict__ bias, const float* __restrict__ res,
                     float* Cf, __nv_bfloat16* Chi, __nv_bfloat16* Clo,
                     float scale, int N, int K)
{
    mma_gemm_body<MODE>(Agh, Agl, Bgh, Bgl, bias, res, Cf, Chi, Clo, scale,
                        N, K, blockIdx.y * 128, blockIdx.x * 128);
}

// Fused QKV: blockIdx.z picks (W, out); q prescaled by 1/sqrt(DK)=0.125.
__global__ __launch_bounds__(256)
void mma_qkv_kernel(const __nv_bfloat16* __restrict__ Agh, const __nv_bfloat16* __restrict__ Agl)
{
    const int z = blockIdx.z;
    const __nv_bfloat16* Bh = (z == 0) ? g_wqh : (z == 1) ? g_wkh : g_wvh;
    const __nv_bfloat16* Bl = (z == 0) ? g_wql : (z == 1) ? g_wkl : g_wvl;
    __nv_bfloat16* Ch = (z == 0) ? g_qh : (z == 1) ? g_kh : g_vh;
    __nv_bfloat16* Cl = (z == 0) ? g_ql : (z == 1) ? g_kl : g_vl;
    const float scale = (z == 0) ? 0.125f : 1.0f;
    mma_gemm_body<0>(Agh, Agl, Bh, Bl, nullptr, nullptr, nullptr, Ch, Cl, scale,
                     DMODEL, DMODEL, blockIdx.y * 128, blockIdx.x * 128);
}

// =====================================================================
// Tensor-core flash attention on pre-split bf16 Q/K/V (cp.async loads).
// Block: 128 threads (4 warps), one (b,h) head, 64-query tile, Bc=64.
// Warp owns 16 q-rows x all 64 keys -> warp-local softmax.
// smem tiles pitch 72 halves (9x16B, odd -> ldsm conflict-free):
//   Qh Ql Kh Kl Vh Vl Ph Pl, 9216 B each = 73728 B total.
// Output: att as (hi,lo) bf16 split.
// =====================================================================
#define ATTP 72
#define T_QH 0
#define T_QL 1
#define T_KH 2
#define T_KL 3
#define T_VH 4
#define T_VL 5
#define T_PH 6
#define T_PL 7
#define ATT_TILE_B (64 * ATTP * 2)          // 9216 bytes
#define ATT_SMEM_BYTES (8 * ATT_TILE_B)     // 73728 bytes

__global__ __launch_bounds__(128)
void attn_mma_kernel(const __nv_bfloat16* __restrict__ Qh_g, const __nv_bfloat16* __restrict__ Ql_g,
                     const __nv_bfloat16* __restrict__ Kh_g, const __nv_bfloat16* __restrict__ Kl_g,
                     const __nv_bfloat16* __restrict__ Vh_g, const __nv_bfloat16* __restrict__ Vl_g,
                     __nv_bfloat16* __restrict__ Oh_g, __nv_bfloat16* __restrict__ Ol_g)
{
    extern __shared__ __nv_bfloat16 sh[];
    const uint32_t uB = smem_u32(sh);
    __nv_bfloat16* Ph = sh + T_PH * 64 * ATTP;
    __nv_bfloat16* Pl = sh + T_PL * 64 * ATTP;

    const int tid  = threadIdx.x;
    const int lane = tid & 31;
    const int warp = tid >> 5;
    const int qt   = blockIdx.x;            // 0..31
    const int bh   = blockIdx.y;            // 0..63
    const size_t base = ((size_t)(bh >> 4) * 2048) * DMODEL + (size_t)(bh & 15) * 64;
    const size_t qoff = base + (size_t)qt * 64 * DMODEL;

    // cp.async loader mapping: row lr (0..63), 32-half group lh, 4 chunks
    const int lr = tid >> 1;
    const int lh = (tid & 1) * 32;
    const uint32_t dst_row = (uint32_t)(lr * ATTP + lh) * 2;

    // issue Q (grouped with kt=0's K/V commit)
#pragma unroll
    for (int c = 0; c < 4; c++) {
        cp16(uB + T_QH * ATT_TILE_B + dst_row + 16 * c, Qh_g + qoff + (size_t)lr * DMODEL + lh + 8 * c);
        cp16(uB + T_QL * ATT_TILE_B + dst_row + 16 * c, Ql_g + qoff + (size_t)lr * DMODEL + lh + 8 * c);
    }

    const uint32_t frag_a = (uint32_t)(((lane & 15) * ATTP + (lane >> 4) * 8) * 2);
    const uint32_t frag_b = (uint32_t)((((lane & 7) + ((lane >> 3) & 1) * 8) * ATTP
                                        + (lane >> 4) * 8) * 2);
    const uint32_t warp_m = (uint32_t)(warp * 16 * ATTP * 2);

    float o[8][4];
#pragma unroll
    for (int j = 0; j < 8; j++)
#pragma unroll
        for (int r = 0; r < 4; r++) o[j][r] = 0.f;
    float mrun[2] = {-1e30f, -1e30f};
    float lrun[2] = {0.f, 0.f};

    for (int kt = 0; kt < 32; kt++) {
        __syncthreads();   // previous tile fully consumed
        {
            const size_t src = base + (size_t)(kt * 64 + lr) * DMODEL + lh;
#pragma unroll
            for (int c = 0; c < 4; c++) {
                cp16(uB + T_KH * ATT_TILE_B + dst_row + 16 * c, Kh_g + src + 8 * c);
                cp16(uB + T_KL * ATT_TILE_B + dst_row + 16 * c, Kl_g + src + 8 * c);
                cp16(uB + T_VH * ATT_TILE_B + dst_row + 16 * c, Vh_g + src + 8 * c);
                cp16(uB + T_VL * ATT_TILE_B + dst_row + 16 * c, Vl_g + src + 8 * c);
            }
        }
        cp_commit();
        cp_wait<0>();
        __syncthreads();

        // ---- S = Q @ K^T (Q prescaled at QKV epilogue) ----
        float s[8][4];
#pragma unroll
        for (int j = 0; j < 8; j++)
#pragma unroll
            for (int r = 0; r < 4; r++) s[j][r] = 0.f;

#pragma unroll
        for (int ks = 0; ks < 4; ks++) {
            const uint32_t ko = (uint32_t)(ks * 32);   // 16 halves = 32 bytes
            uint32_t qh[4], ql[4];
            ldsm_x4(qh[0], qh[1], qh[2], qh[3], uB + T_QH * ATT_TILE_B + frag_a + warp_m + ko);
            ldsm_x4(ql[0], ql[1], ql[2], ql[3], uB + T_QL * ATT_TILE_B + frag_a + warp_m + ko);
#pragma unroll
            for (int jp = 0; jp < 4; jp++) {
                const uint32_t nb = (uint32_t)(jp * 16 * ATTP * 2);
                uint32_t h0, h1, h2, h3, l0, l1, l2, l3;
                ldsm_x4(h0, h1, h2, h3, uB + T_KH * ATT_TILE_B + frag_a + nb + ko);
                ldsm_x4(l0, l1, l2, l3, uB + T_KL * ATT_TILE_B + frag_a + nb + ko);
                uint32_t bh0[2] = {h0, h2}, bh1[2] = {h1, h3};
                uint32_t bl0[2] = {l0, l2}, bl1[2] = {l1, l3};
                mma16816(s[2 * jp],     qh, bh0);
                mma16816(s[2 * jp],     qh, bl0);
                mma16816(s[2 * jp],     ql, bh0);
                mma16816(s[2 * jp + 1], qh, bh1);
                mma16816(s[2 * jp + 1], qh, bl1);
                mma16816(s[2 * jp + 1], ql, bh1);
            }
        }

        // ---- online softmax (warp-local rows) + split P -> smem ----
#pragma unroll
        for (int h = 0; h < 2; h++) {
            float mt = -1e30f;
#pragma unroll
            for (int j = 0; j < 8; j++)
                mt = fmaxf(mt, fmaxf(s[j][2 * h], s[j][2 * h + 1]));
            mt = fmaxf(mt, __shfl_xor_sync(0xffffffffu, mt, 1));
            mt = fmaxf(mt, __shfl_xor_sync(0xffffffffu, mt, 2));
            const float mnew = fmaxf(mrun[h], mt);
            const float corr = __expf(mrun[h] - mnew);
            mrun[h] = mnew;

            float ls = 0.f;
            const int prow = warp * 16 + (lane >> 2) + 8 * h;
            const int pcb  = 2 * (lane & 3);
#pragma unroll
            for (int j = 0; j < 8; j++) {
                float p0 = __expf(s[j][2 * h]     - mnew);
                float p1 = __expf(s[j][2 * h + 1] - mnew);
                ls += p0 + p1;
                uint32_t hp, lp;
                split2_pack(p0, p1, hp, lp);
                const int idx = prow * ATTP + 8 * j + pcb;
                *(uint32_t*)&Ph[idx] = hp;
                *(uint32_t*)&Pl[idx] = lp;
            }
            ls += __shfl_xor_sync(0xffffffffu, ls, 1);
            ls += __shfl_xor_sync(0xffffffffu, ls, 2);
            lrun[h] = lrun[h] * corr + ls;
#pragma unroll
            for (int j = 0; j < 8; j++) {
                o[j][2 * h]     *= corr;
                o[j][2 * h + 1] *= corr;
            }
        }
        __syncwarp();   // P rows are warp-private; make stores visible to ldsm

        // ---- O += P @ V ----
#pragma unroll
        for (int ks = 0; ks < 4; ks++) {
            const uint32_t ko  = (uint32_t)(ks * 32);
            const uint32_t kvo = (uint32_t)(ks * 16 * ATTP * 2);
            uint32_t ph[4], pl[4];
            ldsm_x4(ph[0], ph[1], ph[2], ph[3], uB + T_PH * ATT_TILE_B + frag_a + warp_m + ko);
            ldsm_x4(pl[0], pl[1], pl[2], pl[3], uB + T_PL * ATT_TILE_B + frag_a + warp_m + ko);
#pragma unroll
            for (int jp = 0; jp < 4; jp++) {
                const uint32_t nb = (uint32_t)(16 * jp * 2);
                uint32_t h0, h1, h2, h3, l0, l1, l2, l3;
                ldsm_x4t(h0, h1, h2, h3, uB + T_VH * ATT_TILE_B + frag_b + kvo + nb);
                ldsm_x4t(l0, l1, l2, l3, uB + T_VL * ATT_TILE_B + frag_b + kvo + nb);
                uint32_t bh0[2] = {h0, h1}, bh1[2] = {h2, h3};
                uint32_t bl0[2] = {l0, l1}, bl1[2] = {l2, l3};
                mma16816(o[2 * jp],     ph, bh0);
                mma16816(o[2 * jp],     ph, bl0);
                mma16816(o[2 * jp],     pl, bh0);
                mma16816(o[2 * jp + 1], ph, bh1);
                mma16816(o[2 * jp + 1], ph, bl1);
                mma16816(o[2 * jp + 1], pl, bh1);
            }
        }
    }

    // ---- epilogue: (O / l) -> split bf16 ----
#pragma unroll
    for (int h = 0; h < 2; h++) {
        const float inv = 1.f / lrun[h];
        const int row = warp * 16 + (lane >> 2) + 8 * h;
#pragma unroll
        for (int j = 0; j < 8; j++) {
            const int col = 8 * j + 2 * (lane & 3);
            const size_t off = qoff + (size_t)row * DMODEL + col;
            uint32_t hp, lp;
            split2_pack(o[j][2 * h] * inv, o[j][2 * h + 1] * inv, hp, lp);
            *(uint32_t*)&Oh_g[off] = hp;
            *(uint32_t*)&Ol_g[off] = lp;
        }
    }
}

// =====================================================================
// launch
// =====================================================================
extern "C" void kernel_launch(void* const* d_in, const int* in_sizes, int n_in,
                              void* d_out, int out_size)
{
    (void)in_sizes; (void)n_in; (void)out_size;
    const float* x    = (const float*)d_in[0];
    const float* Wq   = (const float*)d_in[1];
    const float* Wk   = (const float*)d_in[2];
    const float* Wv   = (const float*)d_in[3];
    const float* Wo   = (const float*)d_in[4];
    const float* ln1g = (const float*)d_in[5];
    const float* ln1b = (const float*)d_in[6];
    const float* fc1w = (const float*)d_in[7];
    const float* fc1b = (const float*)d_in[8];
    const float* fc2w = (const float*)d_in[9];
    const float* fc2b = (const float*)d_in[10];
    const float* ln2g = (const float*)d_in[11];
    const float* ln2b = (const float*)d_in[12];
    float* out = (float*)d_out;

    void *xnh, *xnl, *qh, *ql, *kh, *kl, *vh, *vl, *ath, *atl, *hh, *hl, *ffh, *ffl;
    void *wqh, *wql, *wkh, *wkl, *wvh, *wvl, *woh, *wol, *f1h, *f1l, *f2h, *f2l;
    cudaGetSymbolAddress(&xnh, g_xnh); cudaGetSymbolAddress(&xnl, g_xnl);
    cudaGetSymbolAddress(&qh,  g_qh);  cudaGetSymbolAddress(&ql,  g_ql);
    cudaGetSymbolAddress(&kh,  g_kh);  cudaGetSymbolAddress(&kl,  g_kl);
    cudaGetSymbolAddress(&vh,  g_vh);  cudaGetSymbolAddress(&vl,  g_vl);
    cudaGetSymbolAddress(&ath, g_ath); cudaGetSymbolAddress(&atl, g_atl);
    cudaGetSymbolAddress(&hh,  g_hh);  cudaGetSymbolAddress(&hl,  g_hl);
    cudaGetSymbolAddress(&ffh, g_ffh); cudaGetSymbolAddress(&ffl, g_ffl);
    cudaGetSymbolAddress(&wqh, g_wqh); cudaGetSymbolAddress(&wql, g_wql);
    cudaGetSymbolAddress(&wkh, g_wkh); cudaGetSymbolAddress(&wkl, g_wkl);
    cudaGetSymbolAddress(&wvh, g_wvh); cudaGetSymbolAddress(&wvl, g_wvl);
    cudaGetSymbolAddress(&woh, g_woh); cudaGetSymbolAddress(&wol, g_wol);
    cudaGetSymbolAddress(&f1h, g_f1h); cudaGetSymbolAddress(&f1l, g_f1l);
    cudaGetSymbolAddress(&f2h, g_f2h); cudaGetSymbolAddress(&f2l, g_f2l);

    // dynamic smem opt-in (idempotent)
    cudaFuncSetAttribute(mma_gemm_kernel<1>, cudaFuncAttributeMaxDynamicSharedMemorySize, G_SMEM);
    cudaFuncSetAttribute(mma_gemm_kernel<2>, cudaFuncAttributeMaxDynamicSharedMemorySize, G_SMEM);
    cudaFuncSetAttribute(mma_gemm_kernel<3>, cudaFuncAttributeMaxDynamicSharedMemorySize, G_SMEM);
    cudaFuncSetAttribute(mma_qkv_kernel,     cudaFuncAttributeMaxDynamicSharedMemorySize, G_SMEM);
    cudaFuncSetAttribute(attn_mma_kernel,    cudaFuncAttributeMaxDynamicSharedMemorySize, ATT_SMEM_BYTES);

    // 0) split weights -> (hi,lo) bf16
    const int nD = DMODEL * DMODEL / 4;   // 262144
    const int nF = DMODEL * NFF / 4;      // 524288
    wsplit_kernel<<<nD / 256, 256>>>((const float4*)Wq, (uint2*)wqh, (uint2*)wql, nD);
    wsplit_kernel<<<nD / 256, 256>>>((const float4*)Wk, (uint2*)wkh, (uint2*)wkl, nD);
    wsplit_kernel<<<nD / 256, 256>>>((const float4*)Wv, (uint2*)wvh, (uint2*)wvl, nD);
    wsplit_kernel<<<nD / 256, 256>>>((const float4*)Wo, (uint2*)woh, (uint2*)wol, nD);
    wsplit_kernel<<<nF / 256, 256>>>((const float4*)fc1w, (uint2*)f1h, (uint2*)f1l, nF);
    wsplit_kernel<<<nF / 256, 256>>>((const float4*)fc2w, (uint2*)f2h, (uint2*)f2l, nF);

    // 1) LN1 -> xn (hi,lo)
    ln_kernel<<<NTOK, 256>>>(x, ln1g, ln1b, 1e-5f,
                             (__nv_bfloat16*)xnh, (__nv_bfloat16*)xnl);

    // 2) fused QKV -> q,k,v (hi,lo); q prescaled by 0.125
    dim3 gQKV(DMODEL / 128, NTOK / 128, 3);
    mma_qkv_kernel<<<gQKV, 256, G_SMEM>>>((const __nv_bfloat16*)xnh, (const __nv_bfloat16*)xnl);

    // 3) attention -> att (hi,lo)
    attn_mma_kernel<<<dim3(32, 64), 128, ATT_SMEM_BYTES>>>(
        (const __nv_bfloat16*)qh, (const __nv_bfloat16*)ql,
        (const __nv_bfloat16*)kh, (const __nv_bfloat16*)kl,
        (const __nv_bfloat16*)vh, (const __nv_bfloat16*)vl,
        (__nv_bfloat16*)ath, (__nv_bfloat16*)atl);

    // 4) out = att @ Wo + x   (fp32)
    dim3 gD(DMODEL / 128, NTOK / 128);
    mma_gemm_kernel<1><<<gD, 256, G_SMEM>>>(
        (const __nv_bfloat16*)ath, (const __nv_bfloat16*)atl,
        (const __nv_bfloat16*)woh, (const __nv_bfloat16*)wol,
        nullptr, x, out, nullptr, nullptr, 1.f, DMODEL, DMODEL);

    // 5) LN2 (eps 1e-6) -> h (hi,lo)
    ln_kernel<<<NTOK, 256>>>(out, ln2g, ln2b, 1e-6f,
                             (__nv_bfloat16*)hh, (__nv_bfloat16*)hl);

    // 6) ff = relu(h @ fc1_w + fc1_b) -> (hi,lo)
    dim3 gF(NFF / 128, NTOK / 128);
    mma_gemm_kernel<2><<<gF, 256, G_SMEM>>>(
        (const __nv_bfloat16*)hh, (const __nv_bfloat16*)hl,
        (const __nv_bfloat16*)f1h, (const __nv_bfloat16*)f1l,
        fc1b, nullptr, nullptr, (__nv_bfloat16*)ffh, (__nv_bfloat16*)ffl,
        1.f, NFF, DMODEL);

    // 7) out += ff @ fc2_w + fc2_b   (fp32, in-place accumulate)
    mma_gemm_kernel<3><<<gD, 256, G_SMEM>>>(
        (const __nv_bfloat16*)ffh, (const __nv_bfloat16*)ffl,
        (const __nv_bfloat16*)f2h, (const __nv_bfloat16*)f2l,
        fc2b, out, out, nullptr, nullptr, 1.f, DMODEL, NFF);
}

// round 16
// speedup vs baseline: 1.9231x; 1.1626x over previous
#include <cuda_runtime.h>
#include <cuda_bf16.h>
#include <cstdint>
#include <cstddef>

#define NTOK   8192      // B*S
#define DMODEL 1024
#define NFF    2048

// ---------------- scratch: pre-split bf16 (hi,lo) pairs ----------------
__device__ __nv_bfloat16 g_xnh[NTOK * DMODEL], g_xnl[NTOK * DMODEL];
__device__ __nv_bfloat16 g_qh [NTOK * DMODEL], g_ql [NTOK * DMODEL];
__device__ __nv_bfloat16 g_kh [NTOK * DMODEL], g_kl [NTOK * DMODEL];
__device__ __nv_bfloat16 g_vh [NTOK * DMODEL], g_vl [NTOK * DMODEL];
__device__ __nv_bfloat16 g_ath[NTOK * DMODEL], g_atl[NTOK * DMODEL];
__device__ __nv_bfloat16 g_hh [NTOK * DMODEL], g_hl [NTOK * DMODEL];
__device__ __nv_bfloat16 g_ffh[NTOK * NFF],    g_ffl[NTOK * NFF];
__device__ __nv_bfloat16 g_wqh[DMODEL * DMODEL], g_wql[DMODEL * DMODEL];
__device__ __nv_bfloat16 g_wkh[DMODEL * DMODEL], g_wkl[DMODEL * DMODEL];
__device__ __nv_bfloat16 g_wvh[DMODEL * DMODEL], g_wvl[DMODEL * DMODEL];
__device__ __nv_bfloat16 g_woh[DMODEL * DMODEL], g_wol[DMODEL * DMODEL];
__device__ __nv_bfloat16 g_f1h[DMODEL * NFF],    g_f1l[DMODEL * NFF];
__device__ __nv_bfloat16 g_f2h[NFF * DMODEL],    g_f2l[NFF * DMODEL];

// ---------------- helpers ----------------
__device__ __forceinline__ uint32_t smem_u32(const void* p) {
    return (uint32_t)__cvta_generic_to_shared(p);
}
__device__ __forceinline__ void cp16(uint32_t dst, const void* src) {
    asm volatile("cp.async.cg.shared.global [%0], [%1], 16;\n" :: "r"(dst), "l"(src));
}
__device__ __forceinline__ void cp_commit() {
    asm volatile("cp.async.commit_group;\n");
}
template <int N>
__device__ __forceinline__ void cp_wait() {
    asm volatile("cp.async.wait_group %0;\n" :: "n"(N));
}
__device__ __forceinline__ void ldsm_x4(uint32_t& r0, uint32_t& r1, uint32_t& r2,
                                        uint32_t& r3, uint32_t a) {
    asm volatile("ldmatrix.sync.aligned.m8n8.x4.shared.b16 {%0,%1,%2,%3}, [%4];\n"
                 : "=r"(r0), "=r"(r1), "=r"(r2), "=r"(r3) : "r"(a));
}
__device__ __forceinline__ void ldsm_x4t(uint32_t& r0, uint32_t& r1, uint32_t& r2,
                                         uint32_t& r3, uint32_t a) {
    asm volatile("ldmatrix.sync.aligned.m8n8.x4.trans.shared.b16 {%0,%1,%2,%3}, [%4];\n"
                 : "=r"(r0), "=r"(r1), "=r"(r2), "=r"(r3) : "r"(a));
}
__device__ __forceinline__ void mma16816(float* d, const uint32_t* a, const uint32_t* b) {
    asm volatile(
        "mma.sync.aligned.m16n8k16.row.col.f32.bf16.bf16.f32 "
        "{%0,%1,%2,%3}, {%4,%5,%6,%7}, {%8,%9}, {%0,%1,%2,%3};\n"
        : "+f"(d[0]), "+f"(d[1]), "+f"(d[2]), "+f"(d[3])
        : "r"(a[0]), "r"(a[1]), "r"(a[2]), "r"(a[3]), "r"(b[0]), "r"(b[1]));
}

// split 2 fp32 -> packed bf16 hi pair + lo pair
__device__ __forceinline__ void split2_pack(float v0, float v1,
                                            uint32_t& hp, uint32_t& lp) {
    __nv_bfloat16 h0 = __float2bfloat16(v0);
    __nv_bfloat16 h1 = __float2bfloat16(v1);
    __nv_bfloat16 l0 = __float2bfloat16(v0 - __bfloat162float(h0));
    __nv_bfloat16 l1 = __float2bfloat16(v1 - __bfloat162float(h1));
    hp = (uint32_t)__bfloat16_as_ushort(h0) | ((uint32_t)__bfloat16_as_ushort(h1) << 16);
    lp = (uint32_t)__bfloat16_as_ushort(l0) | ((uint32_t)__bfloat16_as_ushort(l1) << 16);
}
__device__ __forceinline__ void split4_pack(float4 f, uint2& hp, uint2& lp) {
    split2_pack(f.x, f.y, hp.x, lp.x);
    split2_pack(f.z, f.w, hp.y, lp.y);
}

// =====================================================================
// weight split: fp32 -> (hi,lo) bf16
// =====================================================================
__global__ __launch_bounds__(256)
void wsplit_kernel(const float4* __restrict__ in, uint2* __restrict__ oh,
                   uint2* __restrict__ ol, int n4)
{
    int i = blockIdx.x * 256 + threadIdx.x;
    if (i >= n4) return;
    uint2 hp, lp;
    split4_pack(in[i], hp, lp);
    oh[i] = hp;
    ol[i] = lp;
}

// =====================================================================
// LayerNorm: one block per row; output = (hi,lo) bf16 split
// =====================================================================
__global__ __launch_bounds__(256)
void ln_kernel(const float* __restrict__ x, const float* __restrict__ g,
               const float* __restrict__ b, float eps,
               __nv_bfloat16* __restrict__ oh, __nv_bfloat16* __restrict__ ol)
{
    const int tid = threadIdx.x;
    const size_t row = (size_t)blockIdx.x * DMODEL;
    const int c4 = tid * 4;

    float4 v = *(const float4*)(x + row + c4);
    float s = v.x + v.y + v.z + v.w;

    __shared__ float red[8];
    __shared__ float stat[2];

#pragma unroll
    for (int o = 16; o; o >>= 1) s += __shfl_xor_sync(0xffffffffu, s, o);
    if ((tid & 31) == 0) red[tid >> 5] = s;
    __syncthreads();
    if (tid == 0) {
        float t = 0.f;
#pragma unroll
        for (int i = 0; i < 8; i++) t += red[i];
        stat[0] = t * (1.f / DMODEL);
    }
    __syncthreads();
    const float mu = stat[0];

    float dx = v.x - mu, dy = v.y - mu, dz = v.z - mu, dw = v.w - mu;
    float s2 = dx * dx + dy * dy + dz * dz + dw * dw;
#pragma unroll
    for (int o = 16; o; o >>= 1) s2 += __shfl_xor_sync(0xffffffffu, s2, o);
    if ((tid & 31) == 0) red[tid >> 5] = s2;
    __syncthreads();
    if (tid == 0) {
        float t = 0.f;
#pragma unroll
        for (int i = 0; i < 8; i++) t += red[i];
        stat[1] = rsqrtf(t * (1.f / DMODEL) + eps);
    }
    __syncthreads();
    const float rstd = stat[1];

    float4 gg = *(const float4*)(g + c4);
    float4 bb = *(const float4*)(b + c4);
    float4 y;
    y.x = dx * rstd * gg.x + bb.x;
    y.y = dy * rstd * gg.y + bb.y;
    y.z = dz * rstd * gg.z + bb.z;
    y.w = dw * rstd * gg.w + bb.w;
    uint2 hp, lp;
    split4_pack(y, hp, lp);
    *(uint2*)&oh[row + c4] = hp;
    *(uint2*)&ol[row + c4] = lp;
}

// =====================================================================
// Tensor-core GEMM on pre-split bf16 operands, 3-stage cp.async pipeline
// (63KB smem -> 3 CTAs/SM; was 4-stage/84KB/2 CTAs).
//   C = Ah*Bh + Ah*Bl + Al*Bh  (fp32 accumulate)
//   MODE 0: split-out  (Chi/Clo = scale * AB)
//   MODE 1: fp32-out   (Cf = AB + res)
//   MODE 2: split-out  (Chi/Clo = relu(AB + bias))
//   MODE 3: fp32-out   (Cf = AB + bias + res)   (res may alias Cf)
// 128x128 tile, BK=16, 256 threads, 8 warps (2m x 4n, 64x32 warp tiles).
// Loader (coalesced): A arow=tid>>1/ach=(tid&1)*8, B brow=tid>>4/bch=(tid&15)*8.
// smem pitches: A 24 halves, B 136 halves (odd 16B-chunk stride -> ldsm clean).
// =====================================================================
#define BK      16
#define APITCH  24
#define BPITCH  136
#define G_AH    0                      // byte offsets inside one stage
#define G_AL    6144                   // 128*24*2
#define G_BH    12288
#define G_BL    16640                  // +16*136*2
#define G_STAGE 20992
#define G_NSTG  3
#define G_SMEM  (G_NSTG * G_STAGE)     // 62976 bytes

template <int MODE>
__device__ __forceinline__
void mma_gemm_body(const __nv_bfloat16* __restrict__ Agh, const __nv_bfloat16* __restrict__ Agl,
                   const __nv_bfloat16* __restrict__ Bgh, const __nv_bfloat16* __restrict__ Bgl,
                   const float* __restrict__ bias, const float* __restrict__ res,
                   float* Cf, __nv_bfloat16* Chi, __nv_bfloat16* Clo,
                   float scale, int N, int K, int bm, int bn)
{
    extern __shared__ __nv_bfloat16 dsm[];
    const uint32_t uBase = smem_u32(dsm);

    const int tid  = threadIdx.x;
    const int lane = tid & 31;
    const int warp = tid >> 5;
    const int wm   = (warp >> 2) * 64;
    const int wn   = (warp & 3) * 32;

    float acc[4][4][4];
#pragma unroll
    for (int i = 0; i < 4; i++)
#pragma unroll
        for (int j = 0; j < 4; j++)
#pragma unroll
            for (int r = 0; r < 4; r++) acc[i][j][r] = 0.f;

    // cp.async loader mapping (4 x 16B per thread per stage; coalesced)
    const int arow = tid >> 1;            // 0..127
    const int ach  = (tid & 1) * 8;
    const int brow = tid >> 4;            // 0..15
    const int bch  = (tid & 15) * 8;
    const size_t a_src  = (size_t)(bm + arow) * K + ach;
    const size_t b_src0 = (size_t)brow * N + bn + bch;
    const uint32_t a_dst = (uint32_t)(arow * APITCH + ach) * 2;
    const uint32_t b_dst = (uint32_t)(brow * BPITCH + bch) * 2;

    const int niter = K / BK;

    auto issue = [&](int it, int s) {
        const int k0 = it * BK;
        const uint32_t st = uBase + (uint32_t)(s * G_STAGE);
        cp16(st + G_AH + a_dst, Agh + a_src + k0);
        cp16(st + G_AL + a_dst, Agl + a_src + k0);
        cp16(st + G_BH + b_dst, Bgh + b_src0 + (size_t)k0 * N);
        cp16(st + G_BL + b_dst, Bgl + b_src0 + (size_t)k0 * N);
    };

    // fragment lane offsets (bytes)
    const uint32_t a_off = (uint32_t)(((lane & 15) * APITCH + (lane >> 4) * 8) * 2);
    const uint32_t b_off = (uint32_t)((((lane & 7) + ((lane >> 3) & 1) * 8) * BPITCH
                                       + (lane >> 4) * 8) * 2);

    // prologue: stages 0..1
    issue(0, 0); cp_commit();
    issue(1, 1); cp_commit();
    cp_wait<1>();
    __syncthreads();

    int scur = 0;
    for (int i = 0; i < niter; i++) {
        const uint32_t st = uBase + (uint32_t)(scur * G_STAGE);

        // B fragments for 4 n-tiles (hi and lo)
        uint32_t bh[4][2], bl[4][2];
#pragma unroll
        for (int jp = 0; jp < 2; jp++) {
            const uint32_t nb = (uint32_t)((wn + 16 * jp) * 2);
            ldsm_x4t(bh[2 * jp][0], bh[2 * jp][1], bh[2 * jp + 1][0], bh[2 * jp + 1][1],
                     st + G_BH + b_off + nb);
            ldsm_x4t(bl[2 * jp][0], bl[2 * jp][1], bl[2 * jp + 1][0], bl[2 * jp + 1][1],
                     st + G_BL + b_off + nb);
        }

#pragma unroll
        for (int ii = 0; ii < 4; ii++) {
            const uint32_t mb = (uint32_t)((wm + 16 * ii) * APITCH * 2);
            uint32_t ah[4], al[4];
            ldsm_x4(ah[0], ah[1], ah[2], ah[3], st + G_AH + a_off + mb);
            ldsm_x4(al[0], al[1], al[2], al[3], st + G_AL + a_off + mb);
#pragma unroll
            for (int j = 0; j < 4; j++) {
                mma16816(acc[ii][j], ah, bh[j]);
                mma16816(acc[ii][j], ah, bl[j]);
                mma16816(acc[ii][j], al, bh[j]);
            }
        }

        const int nx = i + 2;
        int snx = scur + 2; if (snx >= G_NSTG) snx -= G_NSTG;
        if (nx < niter) issue(nx, snx);
        cp_commit();
        cp_wait<1>();
        __syncthreads();
        scur = (scur + 1 == G_NSTG) ? 0 : scur + 1;
    }

    // epilogue
    const int r0 = lane >> 2;
    const int c0 = (lane & 3) * 2;
#pragma unroll
    for (int i = 0; i < 4; i++) {
        const int row = bm + wm + 16 * i + r0;
#pragma unroll
        for (int j = 0; j < 4; j++) {
            const int col = bn + wn + 8 * j + c0;
#pragma unroll
            for (int h = 0; h < 2; h++) {
                const size_t off = (size_t)(row + 8 * h) * N + col;
                float v0 = acc[i][j][2 * h + 0];
                float v1 = acc[i][j][2 * h + 1];
                if (MODE == 0) { v0 *= scale; v1 *= scale; }
                if (MODE == 1) { v0 += res[off]; v1 += res[off + 1]; }
                if (MODE == 2) {
                    v0 = fmaxf(v0 + bias[col], 0.f);
                    v1 = fmaxf(v1 + bias[col + 1], 0.f);
                }
                if (MODE == 3) {
                    v0 += bias[col] + res[off];
                    v1 += bias[col + 1] + res[off + 1];
                }
                if (MODE == 0 || MODE == 2) {
                    uint32_t hp, lp;
                    split2_pack(v0, v1, hp, lp);
                    *(uint32_t*)&Chi[off] = hp;
                    *(uint32_t*)&Clo[off] = lp;
                } else {
                    float2 o; o.x = v0; o.y = v1;
                    *(float2*)&Cf[off] = o;
                }
            }
        }
    }
}

template <int MODE>
__global__ __launch_bounds__(256)
void mma_gemm_kernel(const __nv_bfloat16* __restrict__ Agh, const __nv_bfloat16* __restrict__ Agl,
                     const __nv_bfloat16* __restrict__ Bgh, const __nv_bfloat16* __restrict__ Bgl,
                     const float* __restrict__ bias, const float* __restrict__ res,
                     float* Cf, __nv_bfloat16* Chi, __nv_bfloat16* Clo,
                     float scale, int N, int K)
{
    mma_gemm_body<MODE>(Agh, Agl, Bgh, Bgl, bias, res, Cf, Chi, Clo, scale,
                        N, K, blockIdx.y * 128, blockIdx.x * 128);
}

// Fused QKV: blockIdx.z picks (W, out); q prescaled by 1/sqrt(DK)=0.125.
__global__ __launch_bounds__(256)
void mma_qkv_kernel(const __nv_bfloat16* __restrict__ Agh, const __nv_bfloat16* __restrict__ Agl)
{
    const int z = blockIdx.z;
    const __nv_bfloat16* Bh = (z == 0) ? g_wqh : (z == 1) ? g_wkh : g_wvh;
    const __nv_bfloat16* Bl = (z == 0) ? g_wql : (z == 1) ? g_wkl : g_wvl;
    __nv_bfloat16* Ch = (z == 0) ? g_qh : (z == 1) ? g_kh : g_vh;
    __nv_bfloat16* Cl = (z == 0) ? g_ql : (z == 1) ? g_kl : g_vl;
    const float scale = (z == 0) ? 0.125f : 1.0f;
    mma_gemm_body<0>(Agh, Agl, Bh, Bl, nullptr, nullptr, nullptr, Ch, Cl, scale,
                     DMODEL, DMODEL, blockIdx.y * 128, blockIdx.x * 128);
}

// =====================================================================
// Tensor-core flash attention, 128-query tile (8 warps, 256 threads).
// One (b,h) head per blockIdx.y, q-tile per blockIdx.x (16 tiles).
// Halves K/V L2 traffic vs the 64-row version (attention is L2-BW bound).
// Warp owns 16 q-rows x all 64 keys -> warp-local softmax (unchanged math).
// smem pitch 72 halves (odd 16B-chunk stride -> ldsm conflict-free):
//   Q 128-row, K/V 64-row, P 128-row, all hi+lo  -> 110592 B, 2 CTAs/SM.
// =====================================================================
#define ATTP   72
#define ROWB   (ATTP * 2)                 // 144 bytes per row
#define OFF_QH 0
#define OFF_QL (128 * ROWB)               // 18432
#define OFF_KH (2 * 128 * ROWB)           // 36864
#define OFF_KL (OFF_KH + 64 * ROWB)       // 46080
#define OFF_VH (OFF_KL + 64 * ROWB)       // 55296
#define OFF_VL (OFF_VH + 64 * ROWB)       // 64512
#define OFF_PH (OFF_VL + 64 * ROWB)       // 73728
#define OFF_PL (OFF_PH + 128 * ROWB)      // 92160
#define ATT_SMEM_BYTES (OFF_PL + 128 * ROWB)   // 110592

__global__ __launch_bounds__(256)
void attn_mma_kernel(const __nv_bfloat16* __restrict__ Qh_g, const __nv_bfloat16* __restrict__ Ql_g,
                     const __nv_bfloat16* __restrict__ Kh_g, const __nv_bfloat16* __restrict__ Kl_g,
                     const __nv_bfloat16* __restrict__ Vh_g, const __nv_bfloat16* __restrict__ Vl_g,
                     __nv_bfloat16* __restrict__ Oh_g, __nv_bfloat16* __restrict__ Ol_g)
{
    extern __shared__ __nv_bfloat16 sh[];
    const uint32_t uB = smem_u32(sh);
    __nv_bfloat16* Ph = sh + OFF_PH / 2;
    __nv_bfloat16* Pl = sh + OFF_PL / 2;

    const int tid  = threadIdx.x;
    const int lane = tid & 31;
    const int warp = tid >> 5;              // 0..7
    const int qt   = blockIdx.x;            // 0..15
    const int bh   = blockIdx.y;            // 0..63
    const size_t base = ((size_t)(bh >> 4) * 2048) * DMODEL + (size_t)(bh & 15) * 64;
    const size_t qoff = base + (size_t)qt * 128 * DMODEL;

    // Q loader: 128 rows, thread -> row tid>>1, 32-half group (tid&1)*32
    {
        const int qlr = tid >> 1;
        const int qlh = (tid & 1) * 32;
        const uint32_t qdst = (uint32_t)(qlr * ATTP + qlh) * 2;
        const size_t qsrc = qoff + (size_t)qlr * DMODEL + qlh;
#pragma unroll
        for (int c = 0; c < 4; c++) {
            cp16(uB + OFF_QH + qdst + 16 * c, Qh_g + qsrc + 8 * c);
            cp16(uB + OFF_QL + qdst + 16 * c, Ql_g + qsrc + 8 * c);
        }
    }

    // K/V loader: 64 rows, thread -> row tid>>2, 16-half group (tid&3)*16
    const int kr = tid >> 2;
    const int kc = (tid & 3) * 16;
    const uint32_t kdst = (uint32_t)(kr * ATTP + kc) * 2;

    const uint32_t frag_a = (uint32_t)(((lane & 15) * ATTP + (lane >> 4) * 8) * 2);
    const uint32_t frag_b = (uint32_t)((((lane & 7) + ((lane >> 3) & 1) * 8) * ATTP
                                        + (lane >> 4) * 8) * 2);
    const uint32_t warp_m = (uint32_t)(warp * 16 * ROWB);

    float o[8][4];
#pragma unroll
    for (int j = 0; j < 8; j++)
#pragma unroll
        for (int r = 0; r < 4; r++) o[j][r] = 0.f;
    float mrun[2] = {-1e30f, -1e30f};
    float lrun[2] = {0.f, 0.f};

    for (int kt = 0; kt < 32; kt++) {
        __syncthreads();   // previous tile fully consumed
        {
            const size_t src = base + (size_t)(kt * 64 + kr) * DMODEL + kc;
#pragma unroll
            for (int c = 0; c < 2; c++) {
                cp16(uB + OFF_KH + kdst + 16 * c, Kh_g + src + 8 * c);
                cp16(uB + OFF_KL + kdst + 16 * c, Kl_g + src + 8 * c);
                cp16(uB + OFF_VH + kdst + 16 * c, Vh_g + src + 8 * c);
                cp16(uB + OFF_VL + kdst + 16 * c, Vl_g + src + 8 * c);
            }
        }
        cp_commit();
        cp_wait<0>();
        __syncthreads();

        // ---- S = Q @ K^T (Q prescaled at QKV epilogue) ----
        float s[8][4];
#pragma unroll
        for (int j = 0; j < 8; j++)
#pragma unroll
            for (int r = 0; r < 4; r++) s[j][r] = 0.f;

#pragma unroll
        for (int ks = 0; ks < 4; ks++) {
            const uint32_t ko = (uint32_t)(ks * 32);   // 16 halves = 32 bytes
            uint32_t qh[4], ql[4];
            ldsm_x4(qh[0], qh[1], qh[2], qh[3], uB + OFF_QH + frag_a + warp_m + ko);
            ldsm_x4(ql[0], ql[1], ql[2], ql[3], uB + OFF_QL + frag_a + warp_m + ko);
#pragma unroll
            for (int jp = 0; jp < 4; jp++) {
                const uint32_t nb = (uint32_t)(jp * 16 * ROWB);
                uint32_t h0, h1, h2, h3, l0, l1, l2, l3;
                ldsm_x4(h0, h1, h2, h3, uB + OFF_KH + frag_a + nb + ko);
                ldsm_x4(l0, l1, l2, l3, uB + OFF_KL + frag_a + nb + ko);
                uint32_t bh0[2] = {h0, h2}, bh1[2] = {h1, h3};
                uint32_t bl0[2] = {l0, l2}, bl1[2] = {l1, l3};
                mma16816(s[2 * jp],     qh, bh0);
                mma16816(s[2 * jp],     qh, bl0);
                mma16816(s[2 * jp],     ql, bh0);
                mma16816(s[2 * jp + 1], qh, bh1);
                mma16816(s[2 * jp + 1], qh, bl1);
                mma16816(s[2 * jp + 1], ql, bh1);
            }
        }

        // ---- online softmax (warp-local rows) + split P -> smem ----
#pragma unroll
        for (int h = 0; h < 2; h++) {
            float mt = -1e30f;
#pragma unroll
            for (int j = 0; j < 8; j++)
                mt = fmaxf(mt, fmaxf(s[j][2 * h], s[j][2 * h + 1]));
            mt = fmaxf(mt, __shfl_xor_sync(0xffffffffu, mt, 1));
            mt = fmaxf(mt, __shfl_xor_sync(0xffffffffu, mt, 2));
            const float mnew = fmaxf(mrun[h], mt);
            const float corr = __expf(mrun[h] - mnew);
            mrun[h] = mnew;

            float ls = 0.f;
            const int prow = warp * 16 + (lane >> 2) + 8 * h;
            const int pcb  = 2 * (lane & 3);
#pragma unroll
            for (int j = 0; j < 8; j++) {
                float p0 = __expf(s[j][2 * h]     - mnew);
                float p1 = __expf(s[j][2 * h + 1] - mnew);
                ls += p0 + p1;
                uint32_t hp, lp;
                split2_pack(p0, p1, hp, lp);
                const int idx = prow * ATTP + 8 * j + pcb;
                *(uint32_t*)&Ph[idx] = hp;
                *(uint32_t*)&Pl[idx] = lp;
            }
            ls += __shfl_xor_sync(0xffffffffu, ls, 1);
            ls += __shfl_xor_sync(0xffffffffu, ls, 2);
            lrun[h] = lrun[h] * corr + ls;
#pragma unroll
            for (int j = 0; j < 8; j++) {
                o[j][2 * h]     *= corr;
                o[j][2 * h + 1] *= corr;
            }
        }
        __syncwarp();   // P rows are warp-private; make stores visible to ldsm

        // ---- O += P @ V ----
#pragma unroll
        for (int ks = 0; ks < 4; ks++) {
            const uint32_t ko  = (uint32_t)(ks * 32);
            const uint32_t kvo = (uint32_t)(ks * 16 * ROWB);
            uint32_t ph[4], pl[4];
            ldsm_x4(ph[0], ph[1], ph[2], ph[3], uB + OFF_PH + frag_a + warp_m + ko);
            ldsm_x4(pl[0], pl[1], pl[2], pl[3], uB + OFF_PL + frag_a + warp_m + ko);
#pragma unroll
            for (int jp = 0; jp < 4; jp++) {
                const uint32_t nb = (uint32_t)(16 * jp * 2);
                uint32_t h0, h1, h2, h3, l0, l1, l2, l3;
                ldsm_x4t(h0, h1, h2, h3, uB + OFF_VH + frag_b + kvo + nb);
                ldsm_x4t(l0, l1, l2, l3, uB + OFF_VL + frag_b + kvo + nb);
                uint32_t bh0[2] = {h0, h1}, bh1[2] = {h2, h3};
                uint32_t bl0[2] = {l0, l1}, bl1[2] = {l2, l3};
                mma16816(o[2 * jp],     ph, bh0);
                mma16816(o[2 * jp],     ph, bl0);
                mma16816(o[2 * jp],     pl, bh0);
                mma16816(o[2 * jp + 1], ph, bh1);
                mma16816(o[2 * jp + 1], ph, bl1);
                mma16816(o[2 * jp + 1], pl, bh1);
            }
        }
    }

    // ---- epilogue: (O / l) -> split bf16 ----
#pragma unroll
    for (int h = 0; h < 2; h++) {
        const float inv = 1.f / lrun[h];
        const int row = warp * 16 + (lane >> 2) + 8 * h;
#pragma unroll
        for (int j = 0; j < 8; j++) {
            const int col = 8 * j + 2 * (lane & 3);
            const size_t off = qoff + (size_t)row * DMODEL + col;
            uint32_t hp, lp;
            split2_pack(o[j][2 * h] * inv, o[j][2 * h + 1] * inv, hp, lp);
            *(uint32_t*)&Oh_g[off] = hp;
            *(uint32_t*)&Ol_g[off] = lp;
        }
    }
}

// =====================================================================
// launch
// =====================================================================
extern "C" void kernel_launch(void* const* d_in, const int* in_sizes, int n_in,
                              void* d_out, int out_size)
{
    (void)in_sizes; (void)n_in; (void)out_size;
    const float* x    = (const float*)d_in[0];
    const float* Wq   = (const float*)d_in[1];
    const float* Wk   = (const float*)d_in[2];
    const float* Wv   = (const float*)d_in[3];
    const float* Wo   = (const float*)d_in[4];
    const float* ln1g = (const float*)d_in[5];
    const float* ln1b = (const float*)d_in[6];
    const float* fc1w = (const float*)d_in[7];
    const float* fc1b = (const float*)d_in[8];
    const float* fc2w = (const float*)d_in[9];
    const float* fc2b = (const float*)d_in[10];
    const float* ln2g = (const float*)d_in[11];
    const float* ln2b = (const float*)d_in[12];
    float* out = (float*)d_out;

    void *xnh, *xnl, *qh, *ql, *kh, *kl, *vh, *vl, *ath, *atl, *hh, *hl, *ffh, *ffl;
    void *wqh, *wql, *wkh, *wkl, *wvh, *wvl, *woh, *wol, *f1h, *f1l, *f2h, *f2l;
    cudaGetSymbolAddress(&xnh, g_xnh); cudaGetSymbolAddress(&xnl, g_xnl);
    cudaGetSymbolAddress(&qh,  g_qh);  cudaGetSymbolAddress(&ql,  g_ql);
    cudaGetSymbolAddress(&kh,  g_kh);  cudaGetSymbolAddress(&kl,  g_kl);
    cudaGetSymbolAddress(&vh,  g_vh);  cudaGetSymbolAddress(&vl,  g_vl);
    cudaGetSymbolAddress(&ath, g_ath); cudaGetSymbolAddress(&atl, g_atl);
    cudaGetSymbolAddress(&hh,  g_hh);  cudaGetSymbolAddress(&hl,  g_hl);
    cudaGetSymbolAddress(&ffh, g_ffh); cudaGetSymbolAddress(&ffl, g_ffl);
    cudaGetSymbolAddress(&wqh, g_wqh); cudaGetSymbolAddress(&wql, g_wql);
    cudaGetSymbolAddress(&wkh, g_wkh); cudaGetSymbolAddress(&wkl, g_wkl);
    cudaGetSymbolAddress(&wvh, g_wvh); cudaGetSymbolAddress(&wvl, g_wvl);
    cudaGetSymbolAddress(&woh, g_woh); cudaGetSymbolAddress(&wol, g_wol);
    cudaGetSymbolAddress(&f1h, g_f1h); cudaGetSymbolAddress(&f1l, g_f1l);
    cudaGetSymbolAddress(&f2h, g_f2h); cudaGetSymbolAddress(&f2l, g_f2l);

    // dynamic smem opt-in (idempotent)
    cudaFuncSetAttribute(mma_gemm_kernel<1>, cudaFuncAttributeMaxDynamicSharedMemorySize, G_SMEM);
    cudaFuncSetAttribute(mma_gemm_kernel<2>, cudaFuncAttributeMaxDynamicSharedMemorySize, G_SMEM);
    cudaFuncSetAttribute(mma_gemm_kernel<3>, cudaFuncAttributeMaxDynamicSharedMemorySize, G_SMEM);
    cudaFuncSetAttribute(mma_qkv_kernel,     cudaFuncAttributeMaxDynamicSharedMemorySize, G_SMEM);
    cudaFuncSetAttribute(attn_mma_kernel,    cudaFuncAttributeMaxDynamicSharedMemorySize, ATT_SMEM_BYTES);

    // 0) split weights -> (hi,lo) bf16
    const int nD = DMODEL * DMODEL / 4;   // 262144
    const int nF = DMODEL * NFF / 4;      // 524288
    wsplit_kernel<<<nD / 256, 256>>>((const float4*)Wq, (uint2*)wqh, (uint2*)wql, nD);
    wsplit_kernel<<<nD / 256, 256>>>((const float4*)Wk, (uint2*)wkh, (uint2*)wkl, nD);
    wsplit_kernel<<<nD / 256, 256>>>((const float4*)Wv, (uint2*)wvh, (uint2*)wvl, nD);
    wsplit_kernel<<<nD / 256, 256>>>((const float4*)Wo, (uint2*)woh, (uint2*)wol, nD);
    wsplit_kernel<<<nF / 256, 256>>>((const float4*)fc1w, (uint2*)f1h, (uint2*)f1l, nF);
    wsplit_kernel<<<nF / 256, 256>>>((const float4*)fc2w, (uint2*)f2h, (uint2*)f2l, nF);

    // 1) LN1 -> xn (hi,lo)
    ln_kernel<<<NTOK, 256>>>(x, ln1g, ln1b, 1e-5f,
                             (__nv_bfloat16*)xnh, (__nv_bfloat16*)xnl);

    // 2) fused QKV -> q,k,v (hi,lo); q prescaled by 0.125
    dim3 gQKV(DMODEL / 128, NTOK / 128, 3);
    mma_qkv_kernel<<<gQKV, 256, G_SMEM>>>((const __nv_bfloat16*)xnh, (const __nv_bfloat16*)xnl);

    // 3) attention -> att (hi,lo); 128-query tiles
    attn_mma_kernel<<<dim3(16, 64), 256, ATT_SMEM_BYTES>>>(
        (const __nv_bfloat16*)qh, (const __nv_bfloat16*)ql,
        (const __nv_bfloat16*)kh, (const __nv_bfloat16*)kl,
        (const __nv_bfloat16*)vh, (const __nv_bfloat16*)vl,
        (__nv_bfloat16*)ath, (__nv_bfloat16*)atl);

    // 4) out = att @ Wo + x   (fp32)
    dim3 gD(DMODEL / 128, NTOK / 128);
    mma_gemm_kernel<1><<<gD, 256, G_SMEM>>>(
        (const __nv_bfloat16*)ath, (const __nv_bfloat16*)atl,
        (const __nv_bfloat16*)woh, (const __nv_bfloat16*)wol,
        nullptr, x, out, nullptr, nullptr, 1.f, DMODEL, DMODEL);

    // 5) LN2 (eps 1e-6) -> h (hi,lo)
    ln_kernel<<<NTOK, 256>>>(out, ln2g, ln2b, 1e-6f,
                             (__nv_bfloat16*)hh, (__nv_bfloat16*)hl);

    // 6) ff = relu(h @ fc1_w + fc1_b) -> (hi,lo)
    dim3 gF(NFF / 128, NTOK / 128);
    mma_gemm_kernel<2><<<gF, 256, G_SMEM>>>(
        (const __nv_bfloat16*)hh, (const __nv_bfloat16*)hl,
        (const __nv_bfloat16*)f1h, (const __nv_bfloat16*)f1l,
        fc1b, nullptr, nullptr, (__nv_bfloat16*)ffh, (__nv_bfloat16*)ffl,
        1.f, NFF, DMODEL);

    // 7) out += ff @ fc2_w + fc2_b   (fp32, in-place accumulate)
    mma_gemm_kernel<3><<<gD, 256, G_SMEM>>>(
        (const __nv_bfloat16*)ffh, (const __nv_bfloat16*)ffl,
        (const __nv_bfloat16*)f2h, (const __nv_bfloat16*)f2l,
        fc2b, out, out, nullptr, nullptr, 1.f, DMODEL, NFF);
}